// round 5
// baseline (speedup 1.0000x reference)
#include <cuda_runtime.h>
#include <cuda_bf16.h>
#include <cstdint>
#include <math.h>

#define BATCH 8
#define SEQ   1024
#define DM    256
#define DI    512
#define NH    8
#define HD    64
#define NS    64
#define CDIM  640
#define DIP   1160
#define NTOK  (BATCH*SEQ)   // 8192
#define NPAD_IN 1280        // 10*128

// ---------------- device scratch ----------------
__device__ float g_x[NTOK*DM];
__device__ float g_zx[NTOK*DIP];
__device__ float g_xbc[NTOK*CDIM];
__device__ float g_dt[NTOK*NH];
__device__ float g_dA[NTOK*NH];
__device__ float g_ys[NTOK*DI];
__device__ float g_lut[8*DIP];
__device__ float g_psum[BATCH*16*DM];
__device__ float g_pmax[BATCH*16*DM];
__device__ float g_pooled[BATCH*DM];
__device__ __align__(16) __nv_bfloat16 g_a3[NTOK*3*DI];
__device__ __align__(16) __nv_bfloat16 g_x3[NTOK*3*DM];
__device__ __align__(16) __nv_bfloat16 g_w3a[NPAD_IN*3*DM];
__device__ __align__(16) __nv_bfloat16 g_w3b[DM*3*DI];

__device__ __forceinline__ float siluf(float x) { return x / (1.f + expf(-x)); }
__device__ __forceinline__ float geluf(float x) { return 0.5f * x * (1.f + erff(x * 0.7071067811865476f)); }

template<int N> __device__ __forceinline__ void cp_wait() {
    asm volatile("cp.async.wait_group %0;\n" :: "n"(N));
}
__device__ __forceinline__ void cp_commit() {
    asm volatile("cp.async.commit_group;\n");
}

// ---------------- layer-0 in_proj LUT ----------------
__global__ void k_lut(const float* __restrict__ emb, const float* __restrict__ W) {
    __shared__ float se[8*DM];
    for (int i = threadIdx.x; i < 8*DM; i += blockDim.x) se[i] = emb[i];
    __syncthreads();
    int e = blockIdx.x*blockDim.x + threadIdx.x;
    if (e >= DIP) return;
    float acc[8] = {0.f,0.f,0.f,0.f,0.f,0.f,0.f,0.f};
    const float* wr = W + (size_t)e*DM;
    for (int d = 0; d < DM; d++) {
        float wv = wr[d];
        #pragma unroll
        for (int v = 0; v < 8; v++) acc[v] += wv * se[v*DM + d];
    }
    #pragma unroll
    for (int v = 0; v < 8; v++) g_lut[(size_t)v*DIP + e] = acc[v];
}

// ---------------- conv4 + silu + softplus(dt) + dA ----------------
// LUT0: layer-0 reads zxbcdt rows out of the 8-row LUT via ids.
template<bool LUT0>
__global__ void k_conv(const float* __restrict__ cw, const float* __restrict__ cb,
                       const float* __restrict__ dtb, const float* __restrict__ Alog,
                       const int* __restrict__ ids) {
    int bt = blockIdx.x;
    int t  = bt & (SEQ-1);
    const float* rows[4];
    #pragma unroll
    for (int k = 0; k < 4; k++) {
        int tt = t - 3 + k;
        if (tt >= 0) {
            int src = bt - 3 + k;
            rows[k] = LUT0 ? (g_lut + (size_t)ids[src]*DIP) : (g_zx + (size_t)src*DIP);
        } else rows[k] = nullptr;
    }
    for (int c = threadIdx.x; c < CDIM; c += blockDim.x) {
        float acc = cb[c];
        #pragma unroll
        for (int k = 0; k < 4; k++)
            if (rows[k]) acc += rows[k][DI + c] * cw[c*4 + k];
        g_xbc[(size_t)bt*CDIM + c] = siluf(acc);
    }
    if (threadIdx.x < NH) {
        int h = threadIdx.x;
        float xr = (LUT0 ? g_lut[(size_t)ids[bt]*DIP + DI + CDIM + h]
                         : g_zx[(size_t)bt*DIP + DI + CDIM + h]) + dtb[h];
        float dtv = (xr > 20.f) ? xr : log1pf(expf(xr));
        g_dt[bt*NH + h] = dtv;
        g_dA[bt*NH + h] = expf(dtv * (-expf(Alog[h])));
    }
}

// ---------------- SSD scan: 1024 threads per (b,h); 64 p x 16 q, 4 states/thread ----------------
__global__ void __launch_bounds__(1024) k_scan(const float* __restrict__ Dp) {
    int h = blockIdx.x, b = blockIdx.y;
    int tid = threadIdx.x;
    int p = tid >> 4, q = tid & 15;
    float Dh = Dp[h];
    float hreg[4] = {0.f, 0.f, 0.f, 0.f};

    __shared__ float sx[16][64], sB[16][64], sC[16][64];
    __shared__ float sdt[16], sdA[16];

    for (int t0 = 0; t0 < SEQ; t0 += 16) {
        for (int i = tid; i < 16*64; i += 1024) {
            int s = i >> 6, j = i & 63;
            const float* row = g_xbc + (size_t)(b*SEQ + t0 + s)*CDIM;
            sx[s][j] = row[h*HD + j];
            sB[s][j] = row[DI + j];
            sC[s][j] = row[DI + NS + j];
        }
        if (tid < 16) {
            sdt[tid] = g_dt[(b*SEQ + t0 + tid)*NH + h];
            sdA[tid] = g_dA[(b*SEQ + t0 + tid)*NH + h];
        }
        __syncthreads();
        #pragma unroll 4
        for (int s = 0; s < 16; s++) {
            float da  = sdA[s];
            float xv  = sx[s][p];
            float dtx = sdt[s] * xv;
            float y = 0.f;
            #pragma unroll
            for (int i = 0; i < 4; i++) {
                int n = q + 16*i;
                hreg[i] = hreg[i]*da + dtx*sB[s][n];
                y += hreg[i]*sC[s][n];
            }
            y += __shfl_xor_sync(0xffffffffu, y, 1);
            y += __shfl_xor_sync(0xffffffffu, y, 2);
            y += __shfl_xor_sync(0xffffffffu, y, 4);
            y += __shfl_xor_sync(0xffffffffu, y, 8);
            if (q == 0)
                g_ys[(size_t)(b*SEQ + t0 + s)*DI + h*HD + p] = y + xv*Dh;
        }
        __syncthreads();
    }
}

// ---------------- gate + RMSNorm -> bf16 triple g_a3 ----------------
template<bool LUT0>
__global__ void k_gate(const float* __restrict__ nw, const int* __restrict__ ids) {
    int bt = blockIdx.x, tid = threadIdx.x;
    const float* ysr = g_ys + (size_t)bt*DI;
    const float* zr  = LUT0 ? (g_lut + (size_t)ids[bt]*DIP) : (g_zx + (size_t)bt*DIP);
    float v0 = ysr[tid]       * siluf(zr[tid]);
    float v1 = ysr[tid + 256] * siluf(zr[tid + 256]);
    __shared__ float red[256];
    red[tid] = v0*v0 + v1*v1;
    __syncthreads();
    for (int s = 128; s > 0; s >>= 1) {
        if (tid < s) red[tid] += red[tid + s];
        __syncthreads();
    }
    float scale = rsqrtf(red[0] * (1.f/DI) + 1e-5f);
    __nv_bfloat16* a3 = g_a3 + (size_t)bt*(3*DI);
    float y0 = v0*scale*nw[tid];
    float y1 = v1*scale*nw[tid + 256];
    __nv_bfloat16 h0 = __float2bfloat16_rn(y0);
    __nv_bfloat16 l0 = __float2bfloat16_rn(y0 - __bfloat162float(h0));
    __nv_bfloat16 h1 = __float2bfloat16_rn(y1);
    __nv_bfloat16 l1 = __float2bfloat16_rn(y1 - __bfloat162float(h1));
    a3[tid] = h0;  a3[DI + tid] = h0;  a3[2*DI + tid] = l0;
    a3[tid+256] = h1; a3[DI + tid+256] = h1; a3[2*DI + tid+256] = l1;
}

// ---------------- weight triple conversion: W3 = [Wh | Wl | Wh] ----------------
__global__ void k_cvtW(const float* __restrict__ W, __nv_bfloat16* __restrict__ W3,
                       int N, int Npad, int K) {
    int idx = blockIdx.x*blockDim.x + threadIdx.x;
    if (idx >= Npad*K) return;
    int n = idx / K, k = idx % K;
    float w = (n < N) ? W[(size_t)n*K + k] : 0.f;
    __nv_bfloat16 h = __float2bfloat16_rn(w);
    __nv_bfloat16 l = __float2bfloat16_rn(w - __bfloat162float(h));
    __nv_bfloat16* row = W3 + (size_t)n*(3*K);
    row[k] = h; row[K + k] = l; row[2*K + k] = h;
}

// ---------------- pipelined tensor-core GEMM ----------------
// RESID_MODE: 0 none, 1 add R[m][n], 2 add emb[ids[m]][n]
#define GBM 128
#define GBN 128
#define GBK 32

template<int RESID_MODE, bool W3OUT>
__global__ void __launch_bounds__(256) k_mma(
        const __nv_bfloat16* __restrict__ A,   // [M][Kp]
        const __nv_bfloat16* __restrict__ W,   // [Npad][Kp]
        const float* __restrict__ R,
        const int* __restrict__ ids,
        const float* __restrict__ emb,
        float* __restrict__ C,                 // [M][ldc]
        __nv_bfloat16* __restrict__ X3,        // triple out [M][3*N]
        int N, int Kp, int ldc)
{
    __shared__ __nv_bfloat16 As[2][GBM][GBK+8];
    __shared__ __nv_bfloat16 Ws[2][GBN][GBK+8];
    int tid = threadIdx.x;
    int warp = tid >> 5, lane = tid & 31;
    int wm = warp >> 2, wn = warp & 3;
    int m0 = blockIdx.y * GBM;
    int n0 = blockIdx.x * GBN;

    float acc[4][4][4];
    #pragma unroll
    for (int i = 0; i < 4; i++)
        #pragma unroll
        for (int j = 0; j < 4; j++)
            #pragma unroll
            for (int e = 0; e < 4; e++) acc[i][j][e] = 0.f;

    int nk = Kp / GBK;

    auto load_stage = [&](int st, int k0) {
        #pragma unroll
        for (int u = 0; u < 2; u++) {
            int idx = tid + u*256;
            int r = idx >> 2, c = (idx & 3)*8;
            unsigned int da = (unsigned int)__cvta_generic_to_shared(&As[st][r][c]);
            asm volatile("cp.async.cg.shared.global [%0], [%1], 16;\n"
                :: "r"(da), "l"(A + (size_t)(m0 + r)*Kp + k0 + c));
            unsigned int dw = (unsigned int)__cvta_generic_to_shared(&Ws[st][r][c]);
            asm volatile("cp.async.cg.shared.global [%0], [%1], 16;\n"
                :: "r"(dw), "l"(W + (size_t)(n0 + r)*Kp + k0 + c));
        }
    };

    load_stage(0, 0);
    cp_commit();

    for (int it = 0; it < nk; it++) {
        int st = it & 1;
        if (it + 1 < nk) {
            load_stage(st ^ 1, (it + 1)*GBK);
            cp_commit();
            cp_wait<1>();
        } else {
            cp_wait<0>();
        }
        __syncthreads();

        #pragma unroll
        for (int kk = 0; kk < GBK; kk += 16) {
            unsigned int af[4][4];
            #pragma unroll
            for (int i = 0; i < 4; i++) {
                int row = wm*64 + i*16 + (lane & 15);
                int col = kk + ((lane >> 4) << 3);
                unsigned int addr = (unsigned int)__cvta_generic_to_shared(&As[st][row][col]);
                asm volatile("ldmatrix.sync.aligned.m8n8.x4.shared.b16 {%0,%1,%2,%3}, [%4];\n"
                    : "=r"(af[i][0]), "=r"(af[i][1]), "=r"(af[i][2]), "=r"(af[i][3]) : "r"(addr));
            }
            unsigned int bfm[2][4];
            #pragma unroll
            for (int g = 0; g < 2; g++) {
                int row = wn*32 + g*16 + (lane & 15);
                int col = kk + ((lane >> 4) << 3);
                unsigned int addr = (unsigned int)__cvta_generic_to_shared(&Ws[st][row][col]);
                asm volatile("ldmatrix.sync.aligned.m8n8.x4.shared.b16 {%0,%1,%2,%3}, [%4];\n"
                    : "=r"(bfm[g][0]), "=r"(bfm[g][1]), "=r"(bfm[g][2]), "=r"(bfm[g][3]) : "r"(addr));
            }
            #pragma unroll
            for (int i = 0; i < 4; i++) {
                #pragma unroll
                for (int g = 0; g < 2; g++) {
                    #pragma unroll
                    for (int s = 0; s < 2; s++) {
                        int j = g*2 + s;
                        asm volatile(
                            "mma.sync.aligned.m16n8k16.row.col.f32.bf16.bf16.f32 "
                            "{%0,%1,%2,%3}, {%4,%5,%6,%7}, {%8,%9}, {%0,%1,%2,%3};\n"
                            : "+f"(acc[i][j][0]), "+f"(acc[i][j][1]),
                              "+f"(acc[i][j][2]), "+f"(acc[i][j][3])
                            : "r"(af[i][0]), "r"(af[i][1]), "r"(af[i][2]), "r"(af[i][3]),
                              "r"(bfm[g][s]), "r"(bfm[g][s+2]));
                    }
                }
            }
        }
        __syncthreads();
    }

    // epilogue
    #pragma unroll
    for (int i = 0; i < 4; i++) {
        #pragma unroll
        for (int half = 0; half < 2; half++) {
            int m = m0 + wm*64 + i*16 + (lane >> 2) + half*8;
            const float* rrow = nullptr;
            if (RESID_MODE == 1) rrow = R + (size_t)m*ldc;
            if (RESID_MODE == 2) rrow = emb + (size_t)ids[m]*DM;
            #pragma unroll
            for (int j = 0; j < 4; j++) {
                int ncol = n0 + wn*32 + j*8 + (lane & 3)*2;
                #pragma unroll
                for (int e = 0; e < 2; e++) {
                    int n = ncol + e;
                    if (n < N) {
                        float v = acc[i][j][half*2 + e];
                        if (RESID_MODE) v += rrow[n];
                        C[(size_t)m*ldc + n] = v;
                        if (W3OUT) {
                            __nv_bfloat16 h = __float2bfloat16_rn(v);
                            __nv_bfloat16 l = __float2bfloat16_rn(v - __bfloat162float(h));
                            __nv_bfloat16* row = X3 + (size_t)m*(3*N);
                            row[n] = h; row[N + n] = h; row[2*N + n] = l;
                        }
                    }
                }
            }
        }
    }
}

// ---------------- pooling ----------------
__global__ void k_pool1() {
    int seg = blockIdx.x, b = blockIdx.y, d = threadIdx.x;
    float sum = 0.f, mx = -INFINITY;
    for (int i = 0; i < 64; i++) {
        float v = g_x[(size_t)(b*SEQ + seg*64 + i)*DM + d];
        sum += v; mx = fmaxf(mx, v);
    }
    g_psum[(b*16 + seg)*DM + d] = sum;
    g_pmax[(b*16 + seg)*DM + d] = mx;
}
__global__ void k_pool2() {
    int b = blockIdx.x, d = threadIdx.x;
    float sum = 0.f, mx = -INFINITY;
    for (int s = 0; s < 16; s++) {
        sum += g_psum[(b*16 + s)*DM + d];
        mx = fmaxf(mx, g_pmax[(b*16 + s)*DM + d]);
    }
    g_pooled[b*DM + d] = (sum*(1.f/SEQ) + mx)*0.5f;
}

// ---------------- classification head ----------------
__global__ void k_head(const float* __restrict__ pw, const float* __restrict__ pb,
                       const float* __restrict__ c1w, const float* __restrict__ c1b,
                       const float* __restrict__ c2w, const float* __restrict__ c2b,
                       float* __restrict__ out) {
    int b = blockIdx.x, tid = threadIdx.x;
    __shared__ float sp[DM], s1[DM], s2[128];
    sp[tid] = g_pooled[b*DM + tid];
    __syncthreads();
    {
        float acc = pb[tid];
        const float* wr = pw + (size_t)tid*DM;
        for (int d = 0; d < DM; d++) acc += sp[d]*wr[d];
        s1[tid] = geluf(acc);
    }
    __syncthreads();
    if (tid < 128) {
        float acc = c1b[tid];
        const float* wr = c1w + (size_t)tid*DM;
        for (int d = 0; d < DM; d++) acc += s1[d]*wr[d];
        s2[tid] = geluf(acc);
    }
    __syncthreads();
    if (tid < 2) {
        float acc = c2b[tid];
        const float* wr = c2w + tid*128;
        for (int d = 0; d < 128; d++) acc += s2[d]*wr[d];
        out[b*2 + tid] = acc;
    }
}

// ---------------- launch ----------------
extern "C" void kernel_launch(void* const* d_in, const int* in_sizes, int n_in,
                              void* d_out, int out_size) {
    const int*   ids  = (const int*)  d_in[0];
    const float* emb  = (const float*)d_in[1];
    const float* inw  = (const float*)d_in[2];
    const float* cw   = (const float*)d_in[3];
    const float* cb   = (const float*)d_in[4];
    const float* dtb  = (const float*)d_in[5];
    const float* alog = (const float*)d_in[6];
    const float* Dv   = (const float*)d_in[7];
    const float* nw   = (const float*)d_in[8];
    const float* ow   = (const float*)d_in[9];
    const float* pw   = (const float*)d_in[10];
    const float* pb   = (const float*)d_in[11];
    const float* c1w  = (const float*)d_in[12];
    const float* c1b  = (const float*)d_in[13];
    const float* c2w  = (const float*)d_in[14];
    const float* c2b  = (const float*)d_in[15];
    float* out = (float*)d_out;

    float *px, *pzx;
    __nv_bfloat16 *pa3, *px3, *pw3a, *pw3b;
    cudaGetSymbolAddress((void**)&px,   g_x);
    cudaGetSymbolAddress((void**)&pzx,  g_zx);
    cudaGetSymbolAddress((void**)&pa3,  g_a3);
    cudaGetSymbolAddress((void**)&px3,  g_x3);
    cudaGetSymbolAddress((void**)&pw3a, g_w3a);
    cudaGetSymbolAddress((void**)&pw3b, g_w3b);

    // ---- layer 0 (zxbcdt via 8-row LUT; residual via emb gather in epilogue) ----
    k_lut<<<(DIP + 255)/256, 256>>>(emb, inw);
    k_conv<true><<<NTOK, 256>>>(cw, cb, dtb, alog, ids);
    k_scan<<<dim3(NH, BATCH), 1024>>>(Dv);
    k_gate<true><<<NTOK, 256>>>(nw, ids);
    k_cvtW<<<(DM*DI + 255)/256, 256>>>(ow, pw3b, DM, DM, DI);
    k_mma<2, true><<<dim3(DM/GBN, NTOK/GBM), 256>>>(
        pa3, pw3b, nullptr, ids, emb, px, px3, DM, 3*DI, DM);

    // ---- layer 1 ----
    k_cvtW<<<(NPAD_IN*DM + 255)/256, 256>>>(inw + (size_t)DIP*DM, pw3a, DIP, NPAD_IN, DM);
    k_mma<0, false><<<dim3(NPAD_IN/GBN, NTOK/GBM), 256>>>(
        px3, pw3a, nullptr, nullptr, nullptr, pzx, nullptr, DIP, 3*DM, DIP);
    k_conv<false><<<NTOK, 256>>>(cw + (size_t)CDIM*4, cb + CDIM, dtb + NH, alog + NH, ids);
    k_scan<<<dim3(NH, BATCH), 1024>>>(Dv + NH);
    k_gate<false><<<NTOK, 256>>>(nw + DI, ids);
    k_cvtW<<<(DM*DI + 255)/256, 256>>>(ow + (size_t)DM*DI, pw3b, DM, DM, DI);
    k_mma<1, false><<<dim3(DM/GBN, NTOK/GBM), 256>>>(
        pa3, pw3b, px, nullptr, nullptr, px, nullptr, DM, 3*DI, DM);

    k_pool1<<<dim3(16, BATCH), DM>>>();
    k_pool2<<<BATCH, DM>>>();
    k_head<<<BATCH, DM>>>(pw, pb, c1w, c1b, c2w, c2b, out);
}

// round 6
// speedup vs baseline: 1.0042x; 1.0042x over previous
#include <cuda_runtime.h>
#include <cuda_bf16.h>
#include <cstdint>
#include <math.h>

#define BATCH 8
#define SEQ   1024
#define DM    256
#define DI    512
#define NH    8
#define HD    64
#define NS    64
#define CDIM  640
#define DIP   1160
#define NTOK  (BATCH*SEQ)   // 8192
#define NPAD_IN 1280        // 10*128

// ---------------- device scratch ----------------
__device__ __align__(16) float g_x[NTOK*DM];
__device__ __align__(16) float g_zx[NTOK*DIP];
__device__ __align__(16) float g_ys[NTOK*DI];
__device__ __align__(16) float g_lut[8*DIP];
__device__ float g_psum[BATCH*16*DM];
__device__ float g_pmax[BATCH*16*DM];
__device__ float g_pooled[BATCH*DM];
__device__ __align__(16) __nv_bfloat16 g_a3[NTOK*3*DI];
__device__ __align__(16) __nv_bfloat16 g_x3[NTOK*3*DM];
__device__ __align__(16) __nv_bfloat16 g_w3a[NPAD_IN*3*DM];
__device__ __align__(16) __nv_bfloat16 g_w3b[DM*3*DI];

__device__ __forceinline__ float siluf(float x) { return x / (1.f + expf(-x)); }
__device__ __forceinline__ float geluf(float x) { return 0.5f * x * (1.f + erff(x * 0.7071067811865476f)); }

template<int N> __device__ __forceinline__ void cp_wait() {
    asm volatile("cp.async.wait_group %0;\n" :: "n"(N));
}
__device__ __forceinline__ void cp_commit() {
    asm volatile("cp.async.commit_group;\n");
}

// ---------------- layer-0 in_proj LUT ----------------
__global__ void k_lut(const float* __restrict__ emb, const float* __restrict__ W) {
    __shared__ float se[8*DM];
    for (int i = threadIdx.x; i < 8*DM; i += blockDim.x) se[i] = emb[i];
    __syncthreads();
    int e = blockIdx.x*blockDim.x + threadIdx.x;
    if (e >= DIP) return;
    float acc[8] = {0.f,0.f,0.f,0.f,0.f,0.f,0.f,0.f};
    const float* wr = W + (size_t)e*DM;
    for (int d = 0; d < DM; d++) {
        float wv = wr[d];
        #pragma unroll
        for (int v = 0; v < 8; v++) acc[v] += wv * se[v*DM + d];
    }
    #pragma unroll
    for (int v = 0; v < 8; v++) g_lut[(size_t)v*DIP + e] = acc[v];
}

// ---------------- fused conv4+silu+softplus + SSD scan ----------------
// One block per (b,h). 256 threads: p = tid>>2 (0..63), q = tid&3, 16 states/thread.
// Tile = 16 timesteps. Raw zxbcdt rows staged via cp.async (double buffer) with
// 3-row causal halo; conv computed in smem; then sequential recurrence.
template<bool LUT0>
__global__ void __launch_bounds__(256) k_scanf(
        const float* __restrict__ cw, const float* __restrict__ cb,
        const float* __restrict__ dtb, const float* __restrict__ Alog,
        const float* __restrict__ Dp, const int* __restrict__ ids)
{
    const int h = blockIdx.x, b = blockIdx.y;
    const int tid = threadIdx.x;
    const int p = tid >> 2, q = tid & 3;

    __shared__ float raw[2][19][200];   // cols 0..191: [x-slice 64 | B 64 | C 64]
    __shared__ float sxbc[16][200];
    __shared__ float swt[192][4];
    __shared__ float swb[192];
    __shared__ float sdt[16], sdA[16];

    // conv channel for packed col j: j<64 -> h*64+j ; 64<=j<192 -> 448+j
    for (int j = tid; j < 192; j += 256) {
        int ch = (j < 64) ? h*HD + j : 448 + j;
        swb[j] = cb[ch];
        #pragma unroll
        for (int k = 0; k < 4; k++) swt[j][k] = cw[ch*4 + k];
    }

    const float negA = -expf(Alog[h]);
    const float dtbh = dtb[h];
    const float Dh   = Dp[h];
    float hreg[16];
    #pragma unroll
    for (int i = 0; i < 16; i++) hreg[i] = 0.f;

    // xBC base pointer of token t (points at zx col DI)
    auto rowbase = [&](int t) -> const float* {
        int bt = b*SEQ + t;
        return LUT0 ? (g_lut + (size_t)ids[bt]*DIP + DI)
                    : (g_zx + (size_t)bt*DIP + DI);
    };

    // load rows [t0-3, t0+16) into raw[st]; rows r < rmin skipped (pre-zeroed)
    auto load_tile = [&](int st, int t0, int rmin) {
        for (int i = tid; i < 19*48; i += 256) {
            int r = i / 48;
            int j = (i % 48) * 4;
            if (r < rmin) continue;
            const float* base = rowbase(t0 - 3 + r);
            const float* src = (j < 64) ? (base + h*HD + j) : (base + 448 + j);
            unsigned int dst = (unsigned int)__cvta_generic_to_shared(&raw[st][r][j]);
            asm volatile("cp.async.ca.shared.global [%0], [%1], 16;\n" :: "r"(dst), "l"(src));
        }
    };

    // prologue: zero causal halo, load first tile
    for (int i = tid; i < 3*192; i += 256) raw[0][i/192][i%192] = 0.f;
    load_tile(0, 0, 3);
    cp_commit();

    for (int t0 = 0, it = 0; t0 < SEQ; t0 += 16, it++) {
        int st = it & 1;
        if (t0 + 16 < SEQ) {
            load_tile(st ^ 1, t0 + 16, 0);
            cp_commit();
            cp_wait<1>();
        } else {
            cp_wait<0>();
        }
        __syncthreads();

        // conv + silu: sxbc[s][j] over 16x192
        for (int i = tid; i < 16*192; i += 256) {
            int s = i / 192, j = i % 192;
            float acc = swb[j];
            #pragma unroll
            for (int k = 0; k < 4; k++) acc += raw[st][s + k][j] * swt[j][k];
            sxbc[s][j] = siluf(acc);
        }
        // dt / dA for this tile
        if (tid < 16) {
            const float* base = rowbase(t0 + tid);
            float xr = base[CDIM + h] + dtbh;   // zx col DI+CDIM+h
            float dtv = (xr > 20.f) ? xr : log1pf(expf(xr));
            sdt[tid] = dtv;
            sdA[tid] = expf(dtv * negA);
        }
        __syncthreads();

        #pragma unroll 4
        for (int s = 0; s < 16; s++) {
            float da  = sdA[s];
            float xv  = sxbc[s][p];
            float dtx = sdt[s] * xv;
            float y = 0.f;
            #pragma unroll
            for (int i = 0; i < 16; i++) {
                int n = q + 4*i;
                hreg[i] = hreg[i]*da + dtx*sxbc[s][64 + n];
                y += hreg[i]*sxbc[s][128 + n];
            }
            y += __shfl_xor_sync(0xffffffffu, y, 1);
            y += __shfl_xor_sync(0xffffffffu, y, 2);
            if (q == 0)
                g_ys[(size_t)(b*SEQ + t0 + s)*DI + h*HD + p] = y + xv*Dh;
        }
        __syncthreads();
    }
}

// ---------------- gate + RMSNorm -> bf16 triple g_a3 ----------------
template<bool LUT0>
__global__ void k_gate(const float* __restrict__ nw, const int* __restrict__ ids) {
    int bt = blockIdx.x, tid = threadIdx.x;
    const float* ysr = g_ys + (size_t)bt*DI;
    const float* zr  = LUT0 ? (g_lut + (size_t)ids[bt]*DIP) : (g_zx + (size_t)bt*DIP);
    float v0 = ysr[tid]       * siluf(zr[tid]);
    float v1 = ysr[tid + 256] * siluf(zr[tid + 256]);
    __shared__ float red[256];
    red[tid] = v0*v0 + v1*v1;
    __syncthreads();
    for (int s = 128; s > 0; s >>= 1) {
        if (tid < s) red[tid] += red[tid + s];
        __syncthreads();
    }
    float scale = rsqrtf(red[0] * (1.f/DI) + 1e-5f);
    __nv_bfloat16* a3 = g_a3 + (size_t)bt*(3*DI);
    float y0 = v0*scale*nw[tid];
    float y1 = v1*scale*nw[tid + 256];
    __nv_bfloat16 h0 = __float2bfloat16_rn(y0);
    __nv_bfloat16 l0 = __float2bfloat16_rn(y0 - __bfloat162float(h0));
    __nv_bfloat16 h1 = __float2bfloat16_rn(y1);
    __nv_bfloat16 l1 = __float2bfloat16_rn(y1 - __bfloat162float(h1));
    a3[tid] = h0;  a3[DI + tid] = h0;  a3[2*DI + tid] = l0;
    a3[tid+256] = h1; a3[DI + tid+256] = h1; a3[2*DI + tid+256] = l1;
}

// ---------------- weight triple conversion: W3 = [Wh | Wl | Wh] ----------------
__global__ void k_cvtW(const float* __restrict__ W, __nv_bfloat16* __restrict__ W3,
                       int N, int Npad, int K) {
    int idx = blockIdx.x*blockDim.x + threadIdx.x;
    if (idx >= Npad*K) return;
    int n = idx / K, k = idx % K;
    float w = (n < N) ? W[(size_t)n*K + k] : 0.f;
    __nv_bfloat16 h = __float2bfloat16_rn(w);
    __nv_bfloat16 l = __float2bfloat16_rn(w - __bfloat162float(h));
    __nv_bfloat16* row = W3 + (size_t)n*(3*K);
    row[k] = h; row[K + k] = l; row[2*K + k] = h;
}

// ---------------- pipelined tensor-core GEMM ----------------
// RESID_MODE: 0 none, 1 add R[m][n], 2 add emb[ids[m]][n]
#define GBM 128
#define GBN 128
#define GBK 32

template<int RESID_MODE, bool W3OUT>
__global__ void __launch_bounds__(256) k_mma(
        const __nv_bfloat16* __restrict__ A,
        const __nv_bfloat16* __restrict__ W,
        const float* __restrict__ R,
        const int* __restrict__ ids,
        const float* __restrict__ emb,
        float* __restrict__ C,
        __nv_bfloat16* __restrict__ X3,
        int N, int Kp, int ldc)
{
    __shared__ __nv_bfloat16 As[2][GBM][GBK+8];
    __shared__ __nv_bfloat16 Ws[2][GBN][GBK+8];
    int tid = threadIdx.x;
    int warp = tid >> 5, lane = tid & 31;
    int wm = warp >> 2, wn = warp & 3;
    int m0 = blockIdx.y * GBM;
    int n0 = blockIdx.x * GBN;

    float acc[4][4][4];
    #pragma unroll
    for (int i = 0; i < 4; i++)
        #pragma unroll
        for (int j = 0; j < 4; j++)
            #pragma unroll
            for (int e = 0; e < 4; e++) acc[i][j][e] = 0.f;

    int nk = Kp / GBK;

    auto load_stage = [&](int st, int k0) {
        #pragma unroll
        for (int u = 0; u < 2; u++) {
            int idx = tid + u*256;
            int r = idx >> 2, c = (idx & 3)*8;
            unsigned int da = (unsigned int)__cvta_generic_to_shared(&As[st][r][c]);
            asm volatile("cp.async.cg.shared.global [%0], [%1], 16;\n"
                :: "r"(da), "l"(A + (size_t)(m0 + r)*Kp + k0 + c));
            unsigned int dw = (unsigned int)__cvta_generic_to_shared(&Ws[st][r][c]);
            asm volatile("cp.async.cg.shared.global [%0], [%1], 16;\n"
                :: "r"(dw), "l"(W + (size_t)(n0 + r)*Kp + k0 + c));
        }
    };

    load_stage(0, 0);
    cp_commit();

    for (int it = 0; it < nk; it++) {
        int st = it & 1;
        if (it + 1 < nk) {
            load_stage(st ^ 1, (it + 1)*GBK);
            cp_commit();
            cp_wait<1>();
        } else {
            cp_wait<0>();
        }
        __syncthreads();

        #pragma unroll
        for (int kk = 0; kk < GBK; kk += 16) {
            unsigned int af[4][4];
            #pragma unroll
            for (int i = 0; i < 4; i++) {
                int row = wm*64 + i*16 + (lane & 15);
                int col = kk + ((lane >> 4) << 3);
                unsigned int addr = (unsigned int)__cvta_generic_to_shared(&As[st][row][col]);
                asm volatile("ldmatrix.sync.aligned.m8n8.x4.shared.b16 {%0,%1,%2,%3}, [%4];\n"
                    : "=r"(af[i][0]), "=r"(af[i][1]), "=r"(af[i][2]), "=r"(af[i][3]) : "r"(addr));
            }
            unsigned int bfm[2][4];
            #pragma unroll
            for (int g = 0; g < 2; g++) {
                int row = wn*32 + g*16 + (lane & 15);
                int col = kk + ((lane >> 4) << 3);
                unsigned int addr = (unsigned int)__cvta_generic_to_shared(&Ws[st][row][col]);
                asm volatile("ldmatrix.sync.aligned.m8n8.x4.shared.b16 {%0,%1,%2,%3}, [%4];\n"
                    : "=r"(bfm[g][0]), "=r"(bfm[g][1]), "=r"(bfm[g][2]), "=r"(bfm[g][3]) : "r"(addr));
            }
            #pragma unroll
            for (int i = 0; i < 4; i++) {
                #pragma unroll
                for (int g = 0; g < 2; g++) {
                    #pragma unroll
                    for (int s = 0; s < 2; s++) {
                        int j = g*2 + s;
                        asm volatile(
                            "mma.sync.aligned.m16n8k16.row.col.f32.bf16.bf16.f32 "
                            "{%0,%1,%2,%3}, {%4,%5,%6,%7}, {%8,%9}, {%0,%1,%2,%3};\n"
                            : "+f"(acc[i][j][0]), "+f"(acc[i][j][1]),
                              "+f"(acc[i][j][2]), "+f"(acc[i][j][3])
                            : "r"(af[i][0]), "r"(af[i][1]), "r"(af[i][2]), "r"(af[i][3]),
                              "r"(bfm[g][s]), "r"(bfm[g][s+2]));
                    }
                }
            }
        }
        __syncthreads();
    }

    #pragma unroll
    for (int i = 0; i < 4; i++) {
        #pragma unroll
        for (int half = 0; half < 2; half++) {
            int m = m0 + wm*64 + i*16 + (lane >> 2) + half*8;
            const float* rrow = nullptr;
            if (RESID_MODE == 1) rrow = R + (size_t)m*ldc;
            if (RESID_MODE == 2) rrow = emb + (size_t)ids[m]*DM;
            #pragma unroll
            for (int j = 0; j < 4; j++) {
                int ncol = n0 + wn*32 + j*8 + (lane & 3)*2;
                #pragma unroll
                for (int e = 0; e < 2; e++) {
                    int n = ncol + e;
                    if (n < N) {
                        float v = acc[i][j][half*2 + e];
                        if (RESID_MODE) v += rrow[n];
                        C[(size_t)m*ldc + n] = v;
                        if (W3OUT) {
                            __nv_bfloat16 hh = __float2bfloat16_rn(v);
                            __nv_bfloat16 ll = __float2bfloat16_rn(v - __bfloat162float(hh));
                            __nv_bfloat16* row = X3 + (size_t)m*(3*N);
                            row[n] = hh; row[N + n] = hh; row[2*N + n] = ll;
                        }
                    }
                }
            }
        }
    }
}

// ---------------- pooling ----------------
__global__ void k_pool1() {
    int seg = blockIdx.x, b = blockIdx.y, d = threadIdx.x;
    float sum = 0.f, mx = -INFINITY;
    for (int i = 0; i < 64; i++) {
        float v = g_x[(size_t)(b*SEQ + seg*64 + i)*DM + d];
        sum += v; mx = fmaxf(mx, v);
    }
    g_psum[(b*16 + seg)*DM + d] = sum;
    g_pmax[(b*16 + seg)*DM + d] = mx;
}
__global__ void k_pool2() {
    int b = blockIdx.x, d = threadIdx.x;
    float sum = 0.f, mx = -INFINITY;
    for (int s = 0; s < 16; s++) {
        sum += g_psum[(b*16 + s)*DM + d];
        mx = fmaxf(mx, g_pmax[(b*16 + s)*DM + d]);
    }
    g_pooled[b*DM + d] = (sum*(1.f/SEQ) + mx)*0.5f;
}

// ---------------- classification head ----------------
__global__ void k_head(const float* __restrict__ pw, const float* __restrict__ pb,
                       const float* __restrict__ c1w, const float* __restrict__ c1b,
                       const float* __restrict__ c2w, const float* __restrict__ c2b,
                       float* __restrict__ out) {
    int b = blockIdx.x, tid = threadIdx.x;
    __shared__ float sp[DM], s1[DM], s2[128];
    sp[tid] = g_pooled[b*DM + tid];
    __syncthreads();
    {
        float acc = pb[tid];
        const float* wr = pw + (size_t)tid*DM;
        for (int d = 0; d < DM; d++) acc += sp[d]*wr[d];
        s1[tid] = geluf(acc);
    }
    __syncthreads();
    if (tid < 128) {
        float acc = c1b[tid];
        const float* wr = c1w + (size_t)tid*DM;
        for (int d = 0; d < DM; d++) acc += s1[d]*wr[d];
        s2[tid] = geluf(acc);
    }
    __syncthreads();
    if (tid < 2) {
        float acc = c2b[tid];
        const float* wr = c2w + tid*128;
        for (int d = 0; d < 128; d++) acc += s2[d]*wr[d];
        out[b*2 + tid] = acc;
    }
}

// ---------------- launch ----------------
extern "C" void kernel_launch(void* const* d_in, const int* in_sizes, int n_in,
                              void* d_out, int out_size) {
    const int*   ids  = (const int*)  d_in[0];
    const float* emb  = (const float*)d_in[1];
    const float* inw  = (const float*)d_in[2];
    const float* cw   = (const float*)d_in[3];
    const float* cb   = (const float*)d_in[4];
    const float* dtb  = (const float*)d_in[5];
    const float* alog = (const float*)d_in[6];
    const float* Dv   = (const float*)d_in[7];
    const float* nw   = (const float*)d_in[8];
    const float* ow   = (const float*)d_in[9];
    const float* pw   = (const float*)d_in[10];
    const float* pb   = (const float*)d_in[11];
    const float* c1w  = (const float*)d_in[12];
    const float* c1b  = (const float*)d_in[13];
    const float* c2w  = (const float*)d_in[14];
    const float* c2b  = (const float*)d_in[15];
    float* out = (float*)d_out;

    float *px, *pzx;
    __nv_bfloat16 *pa3, *px3, *pw3a, *pw3b;
    cudaGetSymbolAddress((void**)&px,   g_x);
    cudaGetSymbolAddress((void**)&pzx,  g_zx);
    cudaGetSymbolAddress((void**)&pa3,  g_a3);
    cudaGetSymbolAddress((void**)&px3,  g_x3);
    cudaGetSymbolAddress((void**)&pw3a, g_w3a);
    cudaGetSymbolAddress((void**)&pw3b, g_w3b);

    // ---- layer 0 (zxbcdt via 8-row LUT; residual via emb gather in GEMM epilogue) ----
    k_lut<<<(DIP + 255)/256, 256>>>(emb, inw);
    k_scanf<true><<<dim3(NH, BATCH), 256>>>(cw, cb, dtb, alog, Dv, ids);
    k_gate<true><<<NTOK, 256>>>(nw, ids);
    k_cvtW<<<(DM*DI + 255)/256, 256>>>(ow, pw3b, DM, DM, DI);
    k_mma<2, true><<<dim3(DM/GBN, NTOK/GBM), 256>>>(
        pa3, pw3b, nullptr, ids, emb, px, px3, DM, 3*DI, DM);

    // ---- layer 1 ----
    k_cvtW<<<(NPAD_IN*DM + 255)/256, 256>>>(inw + (size_t)DIP*DM, pw3a, DIP, NPAD_IN, DM);
    k_mma<0, false><<<dim3(NPAD_IN/GBN, NTOK/GBM), 256>>>(
        px3, pw3a, nullptr, nullptr, nullptr, pzx, nullptr, DIP, 3*DM, DIP);
    k_scanf<false><<<dim3(NH, BATCH), 256>>>(cw + (size_t)CDIM*4, cb + CDIM,
                                             dtb + NH, alog + NH, Dv + NH, ids);
    k_gate<false><<<NTOK, 256>>>(nw + DI, ids);
    k_cvtW<<<(DM*DI + 255)/256, 256>>>(ow + (size_t)DM*DI, pw3b, DM, DM, DI);
    k_mma<1, false><<<dim3(DM/GBN, NTOK/GBM), 256>>>(
        pa3, pw3b, px, nullptr, nullptr, px, nullptr, DM, 3*DI, DM);

    k_pool1<<<dim3(16, BATCH), DM>>>();
    k_pool2<<<BATCH, DM>>>();
    k_head<<<BATCH, DM>>>(pw, pb, c1w, c1b, c2w, c2b, out);
}

// round 7
// speedup vs baseline: 1.3208x; 1.3153x over previous
#include <cuda_runtime.h>
#include <cuda_bf16.h>
#include <cstdint>
#include <math.h>

#define BATCH 8
#define SEQ   1024
#define DM    256
#define DI    512
#define NH    8
#define HD    64
#define NS    64
#define CDIM  640
#define DIP   1160
#define NTOK  (BATCH*SEQ)   // 8192
#define NPAD_IN 1280        // 10*128
#define NCH   8
#define CHUNK 128           // SEQ / NCH

// ---------------- device scratch ----------------
__device__ __align__(16) float g_x[NTOK*DM];
__device__ __align__(16) float g_zx[NTOK*DIP];
__device__ __align__(16) float g_xbc[NTOK*CDIM];
__device__ float g_dt[NTOK*NH];
__device__ float g_dA[NTOK*NH];
__device__ float g_pi[NTOK*NH];                 // within-chunk inclusive cumprod of dA
__device__ __align__(16) float g_S[BATCH*NH*NCH*HD*NS];  // chunk states / prefix states (8 MB)
__device__ __align__(16) float g_ys[NTOK*DI];
__device__ __align__(16) float g_lut[8*DIP];
__device__ float g_psum[BATCH*16*DM];
__device__ float g_pmax[BATCH*16*DM];
__device__ float g_pooled[BATCH*DM];
__device__ __align__(16) __nv_bfloat16 g_a3[NTOK*3*DI];
__device__ __align__(16) __nv_bfloat16 g_x3[NTOK*3*DM];
__device__ __align__(16) __nv_bfloat16 g_w3a[NPAD_IN*3*DM];
__device__ __align__(16) __nv_bfloat16 g_w3b[DM*3*DI];

__device__ __forceinline__ float siluf(float x) { return x / (1.f + expf(-x)); }
__device__ __forceinline__ float geluf(float x) { return 0.5f * x * (1.f + erff(x * 0.7071067811865476f)); }

template<int N> __device__ __forceinline__ void cp_wait() {
    asm volatile("cp.async.wait_group %0;\n" :: "n"(N));
}
__device__ __forceinline__ void cp_commit() {
    asm volatile("cp.async.commit_group;\n");
}

// ---------------- layer-0 in_proj LUT ----------------
__global__ void k_lut(const float* __restrict__ emb, const float* __restrict__ W) {
    __shared__ float se[8*DM];
    for (int i = threadIdx.x; i < 8*DM; i += blockDim.x) se[i] = emb[i];
    __syncthreads();
    int e = blockIdx.x*blockDim.x + threadIdx.x;
    if (e >= DIP) return;
    float acc[8] = {0.f,0.f,0.f,0.f,0.f,0.f,0.f,0.f};
    const float* wr = W + (size_t)e*DM;
    for (int d = 0; d < DM; d++) {
        float wv = wr[d];
        #pragma unroll
        for (int v = 0; v < 8; v++) acc[v] += wv * se[v*DM + d];
    }
    #pragma unroll
    for (int v = 0; v < 8; v++) g_lut[(size_t)v*DIP + e] = acc[v];
}

// ---------------- conv4 + silu + softplus(dt) + dA ----------------
template<bool LUT0>
__global__ void k_conv(const float* __restrict__ cw, const float* __restrict__ cb,
                       const float* __restrict__ dtb, const float* __restrict__ Alog,
                       const int* __restrict__ ids) {
    int bt = blockIdx.x;
    int t  = bt & (SEQ-1);
    const float* rows[4];
    #pragma unroll
    for (int k = 0; k < 4; k++) {
        int tt = t - 3 + k;
        if (tt >= 0) {
            int src = bt - 3 + k;
            rows[k] = LUT0 ? (g_lut + (size_t)ids[src]*DIP) : (g_zx + (size_t)src*DIP);
        } else rows[k] = nullptr;
    }
    for (int c = threadIdx.x; c < CDIM; c += blockDim.x) {
        float acc = cb[c];
        #pragma unroll
        for (int k = 0; k < 4; k++)
            if (rows[k]) acc += rows[k][DI + c] * cw[c*4 + k];
        g_xbc[(size_t)bt*CDIM + c] = siluf(acc);
    }
    if (threadIdx.x < NH) {
        int h = threadIdx.x;
        float xr = (LUT0 ? g_lut[(size_t)ids[bt]*DIP + DI + CDIM + h]
                         : g_zx[(size_t)bt*DIP + DI + CDIM + h]) + dtb[h];
        float dtv = (xr > 20.f) ? xr : log1pf(expf(xr));
        g_dt[bt*NH + h] = dtv;
        g_dA[bt*NH + h] = expf(dtv * (-expf(Alog[h])));
    }
}

// ---------------- phase 1: local chunk scan (h starts at 0) ----------------
// grid (NH, BATCH, NCH), 256 threads: p = tid>>2, q = tid&3, 16 states/thread.
__global__ void __launch_bounds__(256) k_scan1(const float* __restrict__ Dp) {
    int h = blockIdx.x, b = blockIdx.y, c = blockIdx.z;
    int tid = threadIdx.x;
    int p = tid >> 2, q = tid & 3;
    float Dh = Dp[h];
    float hreg[16];
    #pragma unroll
    for (int i = 0; i < 16; i++) hreg[i] = 0.f;
    float pi = 1.f;

    __shared__ float sx[16][64], sB[16][64], sC[16][64];
    __shared__ float sdt[16], sdA[16];

    int tbase = c*CHUNK;
    for (int tile = 0; tile < CHUNK/16; tile++) {
        int t0 = tbase + tile*16;
        for (int i = tid; i < 16*64; i += 256) {
            int s = i >> 6, j = i & 63;
            const float* row = g_xbc + (size_t)(b*SEQ + t0 + s)*CDIM;
            sx[s][j] = row[h*HD + j];
            sB[s][j] = row[DI + j];
            sC[s][j] = row[DI + NS + j];
        }
        if (tid < 16) {
            sdt[tid] = g_dt[(b*SEQ + t0 + tid)*NH + h];
            sdA[tid] = g_dA[(b*SEQ + t0 + tid)*NH + h];
        }
        __syncthreads();
        #pragma unroll 4
        for (int s = 0; s < 16; s++) {
            float da  = sdA[s];
            pi *= da;
            float xv  = sx[s][p];
            float dtx = sdt[s] * xv;
            float y = 0.f;
            #pragma unroll
            for (int i = 0; i < 16; i++) {
                int n = q + 4*i;
                hreg[i] = hreg[i]*da + dtx*sB[s][n];
                y += hreg[i]*sC[s][n];
            }
            y += __shfl_xor_sync(0xffffffffu, y, 1);
            y += __shfl_xor_sync(0xffffffffu, y, 2);
            if (q == 0)
                g_ys[(size_t)(b*SEQ + t0 + s)*DI + h*HD + p] = y + xv*Dh;
            if (tid == 0)
                g_pi[(b*SEQ + t0 + s)*NH + h] = pi;
        }
        __syncthreads();
    }
    // final local state S_c
    size_t sb = ((size_t)(b*NH + h)*NCH + c)*(HD*NS);
    #pragma unroll
    for (int i = 0; i < 16; i++)
        g_S[sb + p*NS + q + 4*i] = hreg[i];
}

// ---------------- phase 2: sequential chunk-state prefix (in-place: S_c -> H_prefix_c) ----------------
__global__ void __launch_bounds__(256) k_scan2() {
    int h = blockIdx.x, b = blockIdx.y;
    int tid = threadIdx.x;
    float H[16];
    #pragma unroll
    for (int j = 0; j < 16; j++) H[j] = 0.f;
    size_t base = (size_t)(b*NH + h)*NCH*(HD*NS);
    for (int c = 0; c < NCH; c++) {
        float Ac = g_pi[(b*SEQ + c*CHUNK + CHUNK-1)*NH + h];
        size_t off = base + (size_t)c*(HD*NS) + tid*16;
        float Sc[16];
        #pragma unroll
        for (int j = 0; j < 16; j++) Sc[j] = g_S[off + j];
        #pragma unroll
        for (int j = 0; j < 16; j++) {
            float hp = H[j];
            g_S[off + j] = hp;           // H entering chunk c
            H[j] = Ac*hp + Sc[j];
        }
    }
}

// ---------------- phase 3: cross-chunk correction y_t += pi_t * C_t . H_c ----------------
// grid (NH, BATCH, NCH-1); c = z+1. 256 threads: 4 groups of 64 (p-lane).
__global__ void __launch_bounds__(256) k_scan3() {
    int h = blockIdx.x, b = blockIdx.y, c = blockIdx.z + 1;
    int tid = threadIdx.x;
    int pp = tid & 63, g = tid >> 6;

    __shared__ float sH[64][65];
    __shared__ float sC[16][64];
    __shared__ float spi[16];

    size_t hb = ((size_t)(b*NH + h)*NCH + c)*(HD*NS);
    for (int e = tid; e < HD*NS; e += 256)
        sH[e >> 6][e & 63] = g_S[hb + e];

    for (int tile = 0; tile < CHUNK/16; tile++) {
        int t0 = c*CHUNK + tile*16;
        __syncthreads();
        for (int i = tid; i < 16*64; i += 256) {
            int s = i >> 6, n = i & 63;
            sC[s][n] = g_xbc[(size_t)(b*SEQ + t0 + s)*CDIM + DI + NS + n];
        }
        if (tid < 16)
            spi[tid] = g_pi[(b*SEQ + t0 + tid)*NH + h];
        __syncthreads();
        #pragma unroll
        for (int u = 0; u < 4; u++) {
            int s = g*4 + u;
            float y = 0.f;
            #pragma unroll 16
            for (int n = 0; n < 64; n++)
                y += sC[s][n]*sH[pp][n];
            g_ys[(size_t)(b*SEQ + t0 + s)*DI + h*HD + pp] += spi[s]*y;
        }
    }
}

// ---------------- gate + RMSNorm -> bf16 triple g_a3 ----------------
template<bool LUT0>
__global__ void k_gate(const float* __restrict__ nw, const int* __restrict__ ids) {
    int bt = blockIdx.x, tid = threadIdx.x;
    const float* ysr = g_ys + (size_t)bt*DI;
    const float* zr  = LUT0 ? (g_lut + (size_t)ids[bt]*DIP) : (g_zx + (size_t)bt*DIP);
    float v0 = ysr[tid]       * siluf(zr[tid]);
    float v1 = ysr[tid + 256] * siluf(zr[tid + 256]);
    __shared__ float red[256];
    red[tid] = v0*v0 + v1*v1;
    __syncthreads();
    for (int s = 128; s > 0; s >>= 1) {
        if (tid < s) red[tid] += red[tid + s];
        __syncthreads();
    }
    float scale = rsqrtf(red[0] * (1.f/DI) + 1e-5f);
    __nv_bfloat16* a3 = g_a3 + (size_t)bt*(3*DI);
    float y0 = v0*scale*nw[tid];
    float y1 = v1*scale*nw[tid + 256];
    __nv_bfloat16 h0 = __float2bfloat16_rn(y0);
    __nv_bfloat16 l0 = __float2bfloat16_rn(y0 - __bfloat162float(h0));
    __nv_bfloat16 h1 = __float2bfloat16_rn(y1);
    __nv_bfloat16 l1 = __float2bfloat16_rn(y1 - __bfloat162float(h1));
    a3[tid] = h0;  a3[DI + tid] = h0;  a3[2*DI + tid] = l0;
    a3[tid+256] = h1; a3[DI + tid+256] = h1; a3[2*DI + tid+256] = l1;
}

// ---------------- weight triple conversion: W3 = [Wh | Wl | Wh] ----------------
__global__ void k_cvtW(const float* __restrict__ W, __nv_bfloat16* __restrict__ W3,
                       int N, int Npad, int K) {
    int idx = blockIdx.x*blockDim.x + threadIdx.x;
    if (idx >= Npad*K) return;
    int n = idx / K, k = idx % K;
    float w = (n < N) ? W[(size_t)n*K + k] : 0.f;
    __nv_bfloat16 h = __float2bfloat16_rn(w);
    __nv_bfloat16 l = __float2bfloat16_rn(w - __bfloat162float(h));
    __nv_bfloat16* row = W3 + (size_t)n*(3*K);
    row[k] = h; row[K + k] = l; row[2*K + k] = h;
}

// ---------------- pipelined tensor-core GEMM (unchanged from R6) ----------------
#define GBM 128
#define GBN 128
#define GBK 32

template<int RESID_MODE, bool W3OUT>
__global__ void __launch_bounds__(256) k_mma(
        const __nv_bfloat16* __restrict__ A,
        const __nv_bfloat16* __restrict__ W,
        const float* __restrict__ R,
        const int* __restrict__ ids,
        const float* __restrict__ emb,
        float* __restrict__ C,
        __nv_bfloat16* __restrict__ X3,
        int N, int Kp, int ldc)
{
    __shared__ __nv_bfloat16 As[2][GBM][GBK+8];
    __shared__ __nv_bfloat16 Ws[2][GBN][GBK+8];
    int tid = threadIdx.x;
    int warp = tid >> 5, lane = tid & 31;
    int wm = warp >> 2, wn = warp & 3;
    int m0 = blockIdx.y * GBM;
    int n0 = blockIdx.x * GBN;

    float acc[4][4][4];
    #pragma unroll
    for (int i = 0; i < 4; i++)
        #pragma unroll
        for (int j = 0; j < 4; j++)
            #pragma unroll
            for (int e = 0; e < 4; e++) acc[i][j][e] = 0.f;

    int nk = Kp / GBK;

    auto load_stage = [&](int st, int k0) {
        #pragma unroll
        for (int u = 0; u < 2; u++) {
            int idx = tid + u*256;
            int r = idx >> 2, c = (idx & 3)*8;
            unsigned int da = (unsigned int)__cvta_generic_to_shared(&As[st][r][c]);
            asm volatile("cp.async.cg.shared.global [%0], [%1], 16;\n"
                :: "r"(da), "l"(A + (size_t)(m0 + r)*Kp + k0 + c));
            unsigned int dw = (unsigned int)__cvta_generic_to_shared(&Ws[st][r][c]);
            asm volatile("cp.async.cg.shared.global [%0], [%1], 16;\n"
                :: "r"(dw), "l"(W + (size_t)(n0 + r)*Kp + k0 + c));
        }
    };

    load_stage(0, 0);
    cp_commit();

    for (int it = 0; it < nk; it++) {
        int st = it & 1;
        if (it + 1 < nk) {
            load_stage(st ^ 1, (it + 1)*GBK);
            cp_commit();
            cp_wait<1>();
        } else {
            cp_wait<0>();
        }
        __syncthreads();

        #pragma unroll
        for (int kk = 0; kk < GBK; kk += 16) {
            unsigned int af[4][4];
            #pragma unroll
            for (int i = 0; i < 4; i++) {
                int row = wm*64 + i*16 + (lane & 15);
                int col = kk + ((lane >> 4) << 3);
                unsigned int addr = (unsigned int)__cvta_generic_to_shared(&As[st][row][col]);
                asm volatile("ldmatrix.sync.aligned.m8n8.x4.shared.b16 {%0,%1,%2,%3}, [%4];\n"
                    : "=r"(af[i][0]), "=r"(af[i][1]), "=r"(af[i][2]), "=r"(af[i][3]) : "r"(addr));
            }
            unsigned int bfm[2][4];
            #pragma unroll
            for (int g = 0; g < 2; g++) {
                int row = wn*32 + g*16 + (lane & 15);
                int col = kk + ((lane >> 4) << 3);
                unsigned int addr = (unsigned int)__cvta_generic_to_shared(&Ws[st][row][col]);
                asm volatile("ldmatrix.sync.aligned.m8n8.x4.shared.b16 {%0,%1,%2,%3}, [%4];\n"
                    : "=r"(bfm[g][0]), "=r"(bfm[g][1]), "=r"(bfm[g][2]), "=r"(bfm[g][3]) : "r"(addr));
            }
            #pragma unroll
            for (int i = 0; i < 4; i++) {
                #pragma unroll
                for (int g = 0; g < 2; g++) {
                    #pragma unroll
                    for (int s = 0; s < 2; s++) {
                        int j = g*2 + s;
                        asm volatile(
                            "mma.sync.aligned.m16n8k16.row.col.f32.bf16.bf16.f32 "
                            "{%0,%1,%2,%3}, {%4,%5,%6,%7}, {%8,%9}, {%0,%1,%2,%3};\n"
                            : "+f"(acc[i][j][0]), "+f"(acc[i][j][1]),
                              "+f"(acc[i][j][2]), "+f"(acc[i][j][3])
                            : "r"(af[i][0]), "r"(af[i][1]), "r"(af[i][2]), "r"(af[i][3]),
                              "r"(bfm[g][s]), "r"(bfm[g][s+2]));
                    }
                }
            }
        }
        __syncthreads();
    }

    #pragma unroll
    for (int i = 0; i < 4; i++) {
        #pragma unroll
        for (int half = 0; half < 2; half++) {
            int m = m0 + wm*64 + i*16 + (lane >> 2) + half*8;
            const float* rrow = nullptr;
            if (RESID_MODE == 1) rrow = R + (size_t)m*ldc;
            if (RESID_MODE == 2) rrow = emb + (size_t)ids[m]*DM;
            #pragma unroll
            for (int j = 0; j < 4; j++) {
                int ncol = n0 + wn*32 + j*8 + (lane & 3)*2;
                #pragma unroll
                for (int e = 0; e < 2; e++) {
                    int n = ncol + e;
                    if (n < N) {
                        float v = acc[i][j][half*2 + e];
                        if (RESID_MODE) v += rrow[n];
                        C[(size_t)m*ldc + n] = v;
                        if (W3OUT) {
                            __nv_bfloat16 hh = __float2bfloat16_rn(v);
                            __nv_bfloat16 ll = __float2bfloat16_rn(v - __bfloat162float(hh));
                            __nv_bfloat16* row = X3 + (size_t)m*(3*N);
                            row[n] = hh; row[N + n] = hh; row[2*N + n] = ll;
                        }
                    }
                }
            }
        }
    }
}

// ---------------- pooling ----------------
__global__ void k_pool1() {
    int seg = blockIdx.x, b = blockIdx.y, d = threadIdx.x;
    float sum = 0.f, mx = -INFINITY;
    for (int i = 0; i < 64; i++) {
        float v = g_x[(size_t)(b*SEQ + seg*64 + i)*DM + d];
        sum += v; mx = fmaxf(mx, v);
    }
    g_psum[(b*16 + seg)*DM + d] = sum;
    g_pmax[(b*16 + seg)*DM + d] = mx;
}
__global__ void k_pool2() {
    int b = blockIdx.x, d = threadIdx.x;
    float sum = 0.f, mx = -INFINITY;
    for (int s = 0; s < 16; s++) {
        sum += g_psum[(b*16 + s)*DM + d];
        mx = fmaxf(mx, g_pmax[(b*16 + s)*DM + d]);
    }
    g_pooled[b*DM + d] = (sum*(1.f/SEQ) + mx)*0.5f;
}

// ---------------- classification head ----------------
__global__ void k_head(const float* __restrict__ pw, const float* __restrict__ pb,
                       const float* __restrict__ c1w, const float* __restrict__ c1b,
                       const float* __restrict__ c2w, const float* __restrict__ c2b,
                       float* __restrict__ out) {
    int b = blockIdx.x, tid = threadIdx.x;
    __shared__ float sp[DM], s1[DM], s2[128];
    sp[tid] = g_pooled[b*DM + tid];
    __syncthreads();
    {
        float acc = pb[tid];
        const float* wr = pw + (size_t)tid*DM;
        for (int d = 0; d < DM; d++) acc += sp[d]*wr[d];
        s1[tid] = geluf(acc);
    }
    __syncthreads();
    if (tid < 128) {
        float acc = c1b[tid];
        const float* wr = c1w + (size_t)tid*DM;
        for (int d = 0; d < DM; d++) acc += s1[d]*wr[d];
        s2[tid] = geluf(acc);
    }
    __syncthreads();
    if (tid < 2) {
        float acc = c2b[tid];
        const float* wr = c2w + tid*128;
        for (int d = 0; d < 128; d++) acc += s2[d]*wr[d];
        out[b*2 + tid] = acc;
    }
}

// ---------------- launch ----------------
extern "C" void kernel_launch(void* const* d_in, const int* in_sizes, int n_in,
                              void* d_out, int out_size) {
    const int*   ids  = (const int*)  d_in[0];
    const float* emb  = (const float*)d_in[1];
    const float* inw  = (const float*)d_in[2];
    const float* cw   = (const float*)d_in[3];
    const float* cb   = (const float*)d_in[4];
    const float* dtb  = (const float*)d_in[5];
    const float* alog = (const float*)d_in[6];
    const float* Dv   = (const float*)d_in[7];
    const float* nw   = (const float*)d_in[8];
    const float* ow   = (const float*)d_in[9];
    const float* pw   = (const float*)d_in[10];
    const float* pb   = (const float*)d_in[11];
    const float* c1w  = (const float*)d_in[12];
    const float* c1b  = (const float*)d_in[13];
    const float* c2w  = (const float*)d_in[14];
    const float* c2b  = (const float*)d_in[15];
    float* out = (float*)d_out;

    float *px, *pzx;
    __nv_bfloat16 *pa3, *px3, *pw3a, *pw3b;
    cudaGetSymbolAddress((void**)&px,   g_x);
    cudaGetSymbolAddress((void**)&pzx,  g_zx);
    cudaGetSymbolAddress((void**)&pa3,  g_a3);
    cudaGetSymbolAddress((void**)&px3,  g_x3);
    cudaGetSymbolAddress((void**)&pw3a, g_w3a);
    cudaGetSymbolAddress((void**)&pw3b, g_w3b);

    // ---- layer 0 ----
    k_lut<<<(DIP + 255)/256, 256>>>(emb, inw);
    k_conv<true><<<NTOK, 256>>>(cw, cb, dtb, alog, ids);
    k_scan1<<<dim3(NH, BATCH, NCH), 256>>>(Dv);
    k_scan2<<<dim3(NH, BATCH), 256>>>();
    k_scan3<<<dim3(NH, BATCH, NCH-1), 256>>>();
    k_gate<true><<<NTOK, 256>>>(nw, ids);
    k_cvtW<<<(DM*DI + 255)/256, 256>>>(ow, pw3b, DM, DM, DI);
    k_mma<2, true><<<dim3(DM/GBN, NTOK/GBM), 256>>>(
        pa3, pw3b, nullptr, ids, emb, px, px3, DM, 3*DI, DM);

    // ---- layer 1 ----
    k_cvtW<<<(NPAD_IN*DM + 255)/256, 256>>>(inw + (size_t)DIP*DM, pw3a, DIP, NPAD_IN, DM);
    k_mma<0, false><<<dim3(NPAD_IN/GBN, NTOK/GBM), 256>>>(
        px3, pw3a, nullptr, nullptr, nullptr, pzx, nullptr, DIP, 3*DM, DIP);
    k_conv<false><<<NTOK, 256>>>(cw + (size_t)CDIM*4, cb + CDIM, dtb + NH, alog + NH, ids);
    k_scan1<<<dim3(NH, BATCH, NCH), 256>>>(Dv + NH);
    k_scan2<<<dim3(NH, BATCH), 256>>>();
    k_scan3<<<dim3(NH, BATCH, NCH-1), 256>>>();
    k_gate<false><<<NTOK, 256>>>(nw + DI, ids);
    k_cvtW<<<(DM*DI + 255)/256, 256>>>(ow + (size_t)DM*DI, pw3b, DM, DM, DI);
    k_mma<1, false><<<dim3(DM/GBN, NTOK/GBM), 256>>>(
        pa3, pw3b, px, nullptr, nullptr, px, nullptr, DM, 3*DI, DM);

    k_pool1<<<dim3(16, BATCH), DM>>>();
    k_pool2<<<BATCH, DM>>>();
    k_head<<<BATCH, DM>>>(pw, pb, c1w, c1b, c2w, c2b, out);
}

// round 10
// speedup vs baseline: 1.3454x; 1.0186x over previous
#include <cuda_runtime.h>
#include <cuda_bf16.h>
#include <cstdint>
#include <math.h>

#define BATCH 8
#define SEQ   1024
#define DM    256
#define DI    512
#define NH    8
#define HD    64
#define NS    64
#define CDIM  640
#define DIP   1160
#define NTOK  (BATCH*SEQ)   // 8192
#define NPAD_IN 1280        // 10*128
#define NCH   8
#define CHUNK 128           // SEQ / NCH

// ---------------- device scratch ----------------
__device__ __align__(16) float g_x[NTOK*DM];
__device__ __align__(16) float g_zx[NTOK*DIP];
__device__ __align__(16) float g_xbc[NTOK*CDIM];
__device__ float g_dt[NTOK*NH];
__device__ float g_dA[NTOK*NH];
__device__ float g_pi[NTOK*NH];
__device__ __align__(16) float g_S[BATCH*NH*NCH*HD*NS];
__device__ __align__(16) float g_ys[NTOK*DI];
__device__ __align__(16) float g_lut[8*DIP];
__device__ float g_psum[BATCH*16*DM];
__device__ float g_pmax[BATCH*16*DM];
__device__ float g_pooled[BATCH*DM];
__device__ __align__(16) __nv_bfloat16 g_a3[NTOK*3*DI];
__device__ __align__(16) __nv_bfloat16 g_x3[NTOK*3*DM];
__device__ __align__(16) __nv_bfloat16 g_w3a[NPAD_IN*3*DM];
__device__ __align__(16) __nv_bfloat16 g_w3b[DM*3*DI];

__device__ __forceinline__ float siluf(float x) { return x / (1.f + expf(-x)); }
__device__ __forceinline__ float geluf(float x) { return 0.5f * x * (1.f + erff(x * 0.7071067811865476f)); }

template<int N> __device__ __forceinline__ void cp_wait() {
    asm volatile("cp.async.wait_group %0;\n" :: "n"(N));
}
__device__ __forceinline__ void cp_commit() {
    asm volatile("cp.async.commit_group;\n");
}

// ---------------- layer-0 in_proj LUT ----------------
__global__ void k_lut(const float* __restrict__ emb, const float* __restrict__ W) {
    __shared__ float se[8*DM];
    for (int i = threadIdx.x; i < 8*DM; i += blockDim.x) se[i] = emb[i];
    __syncthreads();
    int e = blockIdx.x*blockDim.x + threadIdx.x;
    if (e >= DIP) return;
    float acc[8] = {0.f,0.f,0.f,0.f,0.f,0.f,0.f,0.f};
    const float* wr = W + (size_t)e*DM;
    for (int d = 0; d < DM; d++) {
        float wv = wr[d];
        #pragma unroll
        for (int v = 0; v < 8; v++) acc[v] += wv * se[v*DM + d];
    }
    #pragma unroll
    for (int v = 0; v < 8; v++) g_lut[(size_t)v*DIP + e] = acc[v];
}

// ---------------- conv4 + silu + softplus(dt) + dA ----------------
template<bool LUT0>
__global__ void k_conv(const float* __restrict__ cw, const float* __restrict__ cb,
                       const float* __restrict__ dtb, const float* __restrict__ Alog,
                       const int* __restrict__ ids) {
    int bt = blockIdx.x;
    int t  = bt & (SEQ-1);
    const float* rows[4];
    #pragma unroll
    for (int k = 0; k < 4; k++) {
        int tt = t - 3 + k;
        if (tt >= 0) {
            int src = bt - 3 + k;
            rows[k] = LUT0 ? (g_lut + (size_t)ids[src]*DIP) : (g_zx + (size_t)src*DIP);
        } else rows[k] = nullptr;
    }
    for (int c = threadIdx.x; c < CDIM; c += blockDim.x) {
        float acc = cb[c];
        #pragma unroll
        for (int k = 0; k < 4; k++)
            if (rows[k]) acc += rows[k][DI + c] * cw[c*4 + k];
        g_xbc[(size_t)bt*CDIM + c] = siluf(acc);
    }
    if (threadIdx.x < NH) {
        int h = threadIdx.x;
        float xr = (LUT0 ? g_lut[(size_t)ids[bt]*DIP + DI + CDIM + h]
                         : g_zx[(size_t)bt*DIP + DI + CDIM + h]) + dtb[h];
        float dtv = (xr > 20.f) ? xr : log1pf(expf(xr));
        g_dt[bt*NH + h] = dtv;
        g_dA[bt*NH + h] = expf(dtv * (-expf(Alog[h])));
    }
}

// ---------------- phase 1: local chunk scan ----------------
__global__ void __launch_bounds__(256) k_scan1(const float* __restrict__ Dp) {
    int h = blockIdx.x, b = blockIdx.y, c = blockIdx.z;
    int tid = threadIdx.x;
    int p = tid >> 2, q = tid & 3;
    float Dh = Dp[h];
    float hreg[16];
    #pragma unroll
    for (int i = 0; i < 16; i++) hreg[i] = 0.f;
    float pi = 1.f;

    __shared__ float sx[16][64], sB[16][64], sC[16][64];
    __shared__ float sdt[16], sdA[16];

    int tbase = c*CHUNK;
    for (int tile = 0; tile < CHUNK/16; tile++) {
        int t0 = tbase + tile*16;
        for (int i = tid; i < 16*64; i += 256) {
            int s = i >> 6, j = i & 63;
            const float* row = g_xbc + (size_t)(b*SEQ + t0 + s)*CDIM;
            sx[s][j] = row[h*HD + j];
            sB[s][j] = row[DI + j];
            sC[s][j] = row[DI + NS + j];
        }
        if (tid < 16) {
            sdt[tid] = g_dt[(b*SEQ + t0 + tid)*NH + h];
            sdA[tid] = g_dA[(b*SEQ + t0 + tid)*NH + h];
        }
        __syncthreads();
        #pragma unroll 4
        for (int s = 0; s < 16; s++) {
            float da  = sdA[s];
            pi *= da;
            float xv  = sx[s][p];
            float dtx = sdt[s] * xv;
            float y = 0.f;
            #pragma unroll
            for (int i = 0; i < 16; i++) {
                int n = q + 4*i;
                hreg[i] = hreg[i]*da + dtx*sB[s][n];
                y += hreg[i]*sC[s][n];
            }
            y += __shfl_xor_sync(0xffffffffu, y, 1);
            y += __shfl_xor_sync(0xffffffffu, y, 2);
            if (q == 0)
                g_ys[(size_t)(b*SEQ + t0 + s)*DI + h*HD + p] = y + xv*Dh;
            if (tid == 0)
                g_pi[(b*SEQ + t0 + s)*NH + h] = pi;
        }
        __syncthreads();
    }
    size_t sb = ((size_t)(b*NH + h)*NCH + c)*(HD*NS);
    #pragma unroll
    for (int i = 0; i < 16; i++)
        g_S[sb + p*NS + q + 4*i] = hreg[i];
}

// ---------------- phase 2: chunk-state prefix (software-pipelined loads) ----------------
__global__ void __launch_bounds__(256) k_scan2() {
    int h = blockIdx.x, b = blockIdx.y;
    int tid = threadIdx.x;
    size_t base = (size_t)(b*NH + h)*NCH*(HD*NS);

    float Ac[NCH];
    #pragma unroll
    for (int c = 0; c < NCH; c++)
        Ac[c] = g_pi[(b*SEQ + c*CHUNK + CHUNK-1)*NH + h];

    float H[16], Sc[16];
    #pragma unroll
    for (int j = 0; j < 16; j++) H[j] = 0.f;
    // preload chunk 0
    #pragma unroll
    for (int j = 0; j < 16; j++) Sc[j] = g_S[base + tid*16 + j];

    #pragma unroll
    for (int c = 0; c < NCH; c++) {
        float Sn[16];
        if (c + 1 < NCH) {
            size_t noff = base + (size_t)(c+1)*(HD*NS) + tid*16;
            #pragma unroll
            for (int j = 0; j < 16; j++) Sn[j] = g_S[noff + j];
        }
        size_t off = base + (size_t)c*(HD*NS) + tid*16;
        #pragma unroll
        for (int j = 0; j < 16; j++) {
            float hp = H[j];
            g_S[off + j] = hp;
            H[j] = Ac[c]*hp + Sc[j];
        }
        #pragma unroll
        for (int j = 0; j < 16; j++) Sc[j] = Sn[j];
    }
}

// ---------------- phase 3: cross-chunk correction ----------------
__global__ void __launch_bounds__(256) k_scan3() {
    int h = blockIdx.x, b = blockIdx.y, c = blockIdx.z + 1;
    int tid = threadIdx.x;
    int pp = tid & 63, g = tid >> 6;

    __shared__ float sH[64][65];
    __shared__ float sC[16][64];
    __shared__ float spi[16];

    size_t hb = ((size_t)(b*NH + h)*NCH + c)*(HD*NS);
    for (int e = tid; e < HD*NS; e += 256)
        sH[e >> 6][e & 63] = g_S[hb + e];

    for (int tile = 0; tile < CHUNK/16; tile++) {
        int t0 = c*CHUNK + tile*16;
        __syncthreads();
        for (int i = tid; i < 16*64; i += 256) {
            int s = i >> 6, n = i & 63;
            sC[s][n] = g_xbc[(size_t)(b*SEQ + t0 + s)*CDIM + DI + NS + n];
        }
        if (tid < 16)
            spi[tid] = g_pi[(b*SEQ + t0 + tid)*NH + h];
        __syncthreads();
        #pragma unroll
        for (int u = 0; u < 4; u++) {
            int s = g*4 + u;
            float y = 0.f;
            #pragma unroll 16
            for (int n = 0; n < 64; n++)
                y += sC[s][n]*sH[pp][n];
            g_ys[(size_t)(b*SEQ + t0 + s)*DI + h*HD + pp] += spi[s]*y;
        }
    }
}

// ---------------- gate + RMSNorm -> bf16 triple g_a3 ----------------
template<bool LUT0>
__global__ void k_gate(const float* __restrict__ nw, const int* __restrict__ ids) {
    int bt = blockIdx.x, tid = threadIdx.x;
    const float* ysr = g_ys + (size_t)bt*DI;
    const float* zr  = LUT0 ? (g_lut + (size_t)ids[bt]*DIP) : (g_zx + (size_t)bt*DIP);
    float v0 = ysr[tid]       * siluf(zr[tid]);
    float v1 = ysr[tid + 256] * siluf(zr[tid + 256]);
    __shared__ float red[256];
    red[tid] = v0*v0 + v1*v1;
    __syncthreads();
    for (int s = 128; s > 0; s >>= 1) {
        if (tid < s) red[tid] += red[tid + s];
        __syncthreads();
    }
    float scale = rsqrtf(red[0] * (1.f/DI) + 1e-5f);
    __nv_bfloat16* a3 = g_a3 + (size_t)bt*(3*DI);
    float y0 = v0*scale*nw[tid];
    float y1 = v1*scale*nw[tid + 256];
    __nv_bfloat16 h0 = __float2bfloat16_rn(y0);
    __nv_bfloat16 l0 = __float2bfloat16_rn(y0 - __bfloat162float(h0));
    __nv_bfloat16 h1 = __float2bfloat16_rn(y1);
    __nv_bfloat16 l1 = __float2bfloat16_rn(y1 - __bfloat162float(h1));
    a3[tid] = h0;  a3[DI + tid] = h0;  a3[2*DI + tid] = l0;
    a3[tid+256] = h1; a3[DI + tid+256] = h1; a3[2*DI + tid+256] = l1;
}

// ---------------- weight triple conversion ----------------
__global__ void k_cvtW(const float* __restrict__ W, __nv_bfloat16* __restrict__ W3,
                       int N, int Npad, int K) {
    int idx = blockIdx.x*blockDim.x + threadIdx.x;
    if (idx >= Npad*K) return;
    int n = idx / K, k = idx % K;
    float w = (n < N) ? W[(size_t)n*K + k] : 0.f;
    __nv_bfloat16 h = __float2bfloat16_rn(w);
    __nv_bfloat16 l = __float2bfloat16_rn(w - __bfloat162float(h));
    __nv_bfloat16* row = W3 + (size_t)n*(3*K);
    row[k] = h; row[K + k] = l; row[2*K + k] = h;
}

// ---------------- 3-stage pipelined tensor-core GEMM (mma.sync bf16) ----------------
// RESID_MODE: 0 none, 1 add R[m][n], 2 add emb[ids[m]][n]
#define GBM 128
#define GBN 128
#define GBK 32
#define STG 3
#define LDA (GBK+8)
#define SMEM_MMA (STG*2*GBM*LDA*2)   // bytes: 3 stages x (A+W) x 128x40 bf16 = 61440

template<int RESID_MODE, bool W3OUT>
__global__ void __launch_bounds__(256) k_mma(
        const __nv_bfloat16* __restrict__ A,
        const __nv_bfloat16* __restrict__ W,
        const float* __restrict__ R,
        const int* __restrict__ ids,
        const float* __restrict__ emb,
        float* __restrict__ C,
        __nv_bfloat16* __restrict__ X3,
        int N, int Kp, int ldc)
{
    extern __shared__ __nv_bfloat16 smp[];
    __nv_bfloat16* Asm = smp;                       // [STG][GBM][LDA]
    __nv_bfloat16* Wsm = smp + STG*GBM*LDA;

    int tid = threadIdx.x;
    int warp = tid >> 5, lane = tid & 31;
    int wm = warp >> 2, wn = warp & 3;
    int m0 = blockIdx.y * GBM;
    int n0 = blockIdx.x * GBN;

    float acc[4][4][4];
    #pragma unroll
    for (int i = 0; i < 4; i++)
        #pragma unroll
        for (int j = 0; j < 4; j++)
            #pragma unroll
            for (int e = 0; e < 4; e++) acc[i][j][e] = 0.f;

    int nk = Kp / GBK;

    auto load_stage = [&](int st, int k0) {
        __nv_bfloat16* as = Asm + st*GBM*LDA;
        __nv_bfloat16* ws = Wsm + st*GBM*LDA;
        #pragma unroll
        for (int u = 0; u < 2; u++) {
            int idx = tid + u*256;
            int r = idx >> 2, kc = (idx & 3)*8;
            unsigned da = (unsigned)__cvta_generic_to_shared(as + r*LDA + kc);
            asm volatile("cp.async.cg.shared.global [%0], [%1], 16;\n"
                :: "r"(da), "l"(A + (size_t)(m0 + r)*Kp + k0 + kc));
            unsigned dw = (unsigned)__cvta_generic_to_shared(ws + r*LDA + kc);
            asm volatile("cp.async.cg.shared.global [%0], [%1], 16;\n"
                :: "r"(dw), "l"(W + (size_t)(n0 + r)*Kp + k0 + kc));
        }
    };

    load_stage(0, 0);
    cp_commit();
    load_stage(1, GBK);
    cp_commit();

    for (int it = 0; it < nk; it++) {
        cp_wait<1>();
        __syncthreads();
        if (it + 2 < nk) {
            load_stage((it + 2) % STG, (it + 2)*GBK);
            cp_commit();
        } else {
            cp_commit();   // keep group count pattern for wait<1>
        }
        int st = it % STG;
        __nv_bfloat16* as = Asm + st*GBM*LDA;
        __nv_bfloat16* ws = Wsm + st*GBM*LDA;

        #pragma unroll
        for (int kk = 0; kk < GBK; kk += 16) {
            unsigned af[4][4];
            #pragma unroll
            for (int i = 0; i < 4; i++) {
                int row = wm*64 + i*16 + (lane & 15);
                int col = kk + ((lane >> 4) << 3);
                unsigned addr = (unsigned)__cvta_generic_to_shared(as + row*LDA + col);
                asm volatile("ldmatrix.sync.aligned.m8n8.x4.shared.b16 {%0,%1,%2,%3}, [%4];\n"
                    : "=r"(af[i][0]), "=r"(af[i][1]), "=r"(af[i][2]), "=r"(af[i][3]) : "r"(addr));
            }
            unsigned bfm[2][4];
            #pragma unroll
            for (int g = 0; g < 2; g++) {
                int row = wn*32 + g*16 + (lane & 15);
                int col = kk + ((lane >> 4) << 3);
                unsigned addr = (unsigned)__cvta_generic_to_shared(ws + row*LDA + col);
                asm volatile("ldmatrix.sync.aligned.m8n8.x4.shared.b16 {%0,%1,%2,%3}, [%4];\n"
                    : "=r"(bfm[g][0]), "=r"(bfm[g][1]), "=r"(bfm[g][2]), "=r"(bfm[g][3]) : "r"(addr));
            }
            #pragma unroll
            for (int i = 0; i < 4; i++) {
                #pragma unroll
                for (int g = 0; g < 2; g++) {
                    #pragma unroll
                    for (int s = 0; s < 2; s++) {
                        int j = g*2 + s;
                        asm volatile(
                            "mma.sync.aligned.m16n8k16.row.col.f32.bf16.bf16.f32 "
                            "{%0,%1,%2,%3}, {%4,%5,%6,%7}, {%8,%9}, {%0,%1,%2,%3};\n"
                            : "+f"(acc[i][j][0]), "+f"(acc[i][j][1]),
                              "+f"(acc[i][j][2]), "+f"(acc[i][j][3])
                            : "r"(af[i][0]), "r"(af[i][1]), "r"(af[i][2]), "r"(af[i][3]),
                              "r"(bfm[g][s]), "r"(bfm[g][s+2]));
                    }
                }
            }
        }
    }

    // epilogue
    #pragma unroll
    for (int i = 0; i < 4; i++) {
        #pragma unroll
        for (int half = 0; half < 2; half++) {
            int m = m0 + wm*64 + i*16 + (lane >> 2) + half*8;
            const float* rrow = nullptr;
            if (RESID_MODE == 1) rrow = R + (size_t)m*ldc;
            if (RESID_MODE == 2) rrow = emb + (size_t)ids[m]*DM;
            #pragma unroll
            for (int j = 0; j < 4; j++) {
                int ncol = n0 + wn*32 + j*8 + (lane & 3)*2;
                #pragma unroll
                for (int e = 0; e < 2; e++) {
                    int n = ncol + e;
                    if (n < N) {
                        float v = acc[i][j][half*2 + e];
                        if (RESID_MODE) v += rrow[n];
                        C[(size_t)m*ldc + n] = v;
                        if (W3OUT) {
                            __nv_bfloat16 hh = __float2bfloat16_rn(v);
                            __nv_bfloat16 ll = __float2bfloat16_rn(v - __bfloat162float(hh));
                            __nv_bfloat16* row = X3 + (size_t)m*(3*N);
                            row[n] = hh; row[N + n] = hh; row[2*N + n] = ll;
                        }
                    }
                }
            }
        }
    }
}

// ---------------- pooling ----------------
__global__ void k_pool1() {
    int seg = blockIdx.x, b = blockIdx.y, d = threadIdx.x;
    float sum = 0.f, mx = -INFINITY;
    for (int i = 0; i < 64; i++) {
        float v = g_x[(size_t)(b*SEQ + seg*64 + i)*DM + d];
        sum += v; mx = fmaxf(mx, v);
    }
    g_psum[(b*16 + seg)*DM + d] = sum;
    g_pmax[(b*16 + seg)*DM + d] = mx;
}
__global__ void k_pool2() {
    int b = blockIdx.x, d = threadIdx.x;
    float sum = 0.f, mx = -INFINITY;
    for (int s = 0; s < 16; s++) {
        sum += g_psum[(b*16 + s)*DM + d];
        mx = fmaxf(mx, g_pmax[(b*16 + s)*DM + d]);
    }
    g_pooled[b*DM + d] = (sum*(1.f/SEQ) + mx)*0.5f;
}

// ---------------- classification head ----------------
__global__ void k_head(const float* __restrict__ pw, const float* __restrict__ pb,
                       const float* __restrict__ c1w, const float* __restrict__ c1b,
                       const float* __restrict__ c2w, const float* __restrict__ c2b,
                       float* __restrict__ out) {
    int b = blockIdx.x, tid = threadIdx.x;
    __shared__ float sp[DM], s1[DM], s2[128];
    sp[tid] = g_pooled[b*DM + tid];
    __syncthreads();
    {
        float acc = pb[tid];
        const float* wr = pw + (size_t)tid*DM;
        for (int d = 0; d < DM; d++) acc += sp[d]*wr[d];
        s1[tid] = geluf(acc);
    }
    __syncthreads();
    if (tid < 128) {
        float acc = c1b[tid];
        const float* wr = c1w + (size_t)tid*DM;
        for (int d = 0; d < DM; d++) acc += s1[d]*wr[d];
        s2[tid] = geluf(acc);
    }
    __syncthreads();
    if (tid < 2) {
        float acc = c2b[tid];
        const float* wr = c2w + tid*128;
        for (int d = 0; d < 128; d++) acc += s2[d]*wr[d];
        out[b*2 + tid] = acc;
    }
}

// ---------------- launch ----------------
extern "C" void kernel_launch(void* const* d_in, const int* in_sizes, int n_in,
                              void* d_out, int out_size) {
    const int*   ids  = (const int*)  d_in[0];
    const float* emb  = (const float*)d_in[1];
    const float* inw  = (const float*)d_in[2];
    const float* cw   = (const float*)d_in[3];
    const float* cb   = (const float*)d_in[4];
    const float* dtb  = (const float*)d_in[5];
    const float* alog = (const float*)d_in[6];
    const float* Dv   = (const float*)d_in[7];
    const float* nw   = (const float*)d_in[8];
    const float* ow   = (const float*)d_in[9];
    const float* pw   = (const float*)d_in[10];
    const float* pb   = (const float*)d_in[11];
    const float* c1w  = (const float*)d_in[12];
    const float* c1b  = (const float*)d_in[13];
    const float* c2w  = (const float*)d_in[14];
    const float* c2b  = (const float*)d_in[15];
    float* out = (float*)d_out;

    float *px, *pzx;
    __nv_bfloat16 *pa3, *px3, *pw3a, *pw3b;
    cudaGetSymbolAddress((void**)&px,   g_x);
    cudaGetSymbolAddress((void**)&pzx,  g_zx);
    cudaGetSymbolAddress((void**)&pa3,  g_a3);
    cudaGetSymbolAddress((void**)&px3,  g_x3);
    cudaGetSymbolAddress((void**)&pw3a, g_w3a);
    cudaGetSymbolAddress((void**)&pw3b, g_w3b);

    cudaFuncSetAttribute(k_mma<2, true>,
        cudaFuncAttributeMaxDynamicSharedMemorySize, SMEM_MMA);
    cudaFuncSetAttribute(k_mma<0, false>,
        cudaFuncAttributeMaxDynamicSharedMemorySize, SMEM_MMA);
    cudaFuncSetAttribute(k_mma<1, false>,
        cudaFuncAttributeMaxDynamicSharedMemorySize, SMEM_MMA);

    // ---- layer 0 ----
    k_lut<<<(DIP + 255)/256, 256>>>(emb, inw);
    k_conv<true><<<NTOK, 256>>>(cw, cb, dtb, alog, ids);
    k_scan1<<<dim3(NH, BATCH, NCH), 256>>>(Dv);
    k_scan2<<<dim3(NH, BATCH), 256>>>();
    k_scan3<<<dim3(NH, BATCH, NCH-1), 256>>>();
    k_gate<true><<<NTOK, 256>>>(nw, ids);
    k_cvtW<<<(DM*DI + 255)/256, 256>>>(ow, pw3b, DM, DM, DI);
    k_mma<2, true><<<dim3(DM/GBN, NTOK/GBM), 256, SMEM_MMA>>>(
        pa3, pw3b, nullptr, ids, emb, px, px3, DM, 3*DI, DM);

    // ---- layer 1 ----
    k_cvtW<<<(NPAD_IN*DM + 255)/256, 256>>>(inw + (size_t)DIP*DM, pw3a, DIP, NPAD_IN, DM);
    k_mma<0, false><<<dim3(NPAD_IN/GBN, NTOK/GBM), 256, SMEM_MMA>>>(
        px3, pw3a, nullptr, nullptr, nullptr, pzx, nullptr, DIP, 3*DM, DIP);
    k_conv<false><<<NTOK, 256>>>(cw + (size_t)CDIM*4, cb + CDIM, dtb + NH, alog + NH, ids);
    k_scan1<<<dim3(NH, BATCH, NCH), 256>>>(Dv + NH);
    k_scan2<<<dim3(NH, BATCH), 256>>>();
    k_scan3<<<dim3(NH, BATCH, NCH-1), 256>>>();
    k_gate<false><<<NTOK, 256>>>(nw + DI, ids);
    k_cvtW<<<(DM*DI + 255)/256, 256>>>(ow + (size_t)DM*DI, pw3b, DM, DM, DI);
    k_mma<1, false><<<dim3(DM/GBN, NTOK/GBM), 256, SMEM_MMA>>>(
        pa3, pw3b, px, nullptr, nullptr, px, nullptr, DM, 3*DI, DM);

    k_pool1<<<dim3(16, BATCH), DM>>>();
    k_pool2<<<BATCH, DM>>>();
    k_head<<<BATCH, DM>>>(pw, pb, c1w, c1b, c2w, c2b, out);
}

// round 11
// speedup vs baseline: 1.4539x; 1.0807x over previous
#include <cuda_runtime.h>
#include <cuda_fp16.h>
#include <cstdint>
#include <math.h>

#define BATCH 8
#define SEQ   1024
#define DM    256
#define DI    512
#define NH    8
#define HD    64
#define NS    64
#define CDIM  640
#define DIP   1160
#define NTOK  (BATCH*SEQ)   // 8192
#define NPAD_IN 1280        // 10*128
#define NCH   8
#define CHUNK 128           // SEQ / NCH

// ---------------- device scratch ----------------
__device__ __align__(16) float g_x[NTOK*DM];
__device__ __align__(16) float g_zx[NTOK*DIP];
__device__ __align__(16) float g_xbc[NTOK*CDIM];
__device__ float g_dt[NTOK*NH];
__device__ float g_dA[NTOK*NH];
__device__ float g_pi[NTOK*NH];
__device__ __align__(16) float g_S[BATCH*NH*NCH*HD*NS];
__device__ __align__(16) float g_ys[NTOK*DI];
__device__ __align__(16) float g_lut[8*DIP];
__device__ float g_psum[BATCH*16*DM];
__device__ float g_pmax[BATCH*16*DM];
__device__ float g_pooled[BATCH*DM];
// fp16 2-term GEMM operands: A2 = [Ah | Al], W2 = [Wf | Wf]
__device__ __align__(16) __half g_a2[NTOK*2*DI];
__device__ __align__(16) __half g_x2[NTOK*2*DM];
__device__ __align__(16) __half g_w2a[NPAD_IN*2*DM];
__device__ __align__(16) __half g_w2b[DM*2*DI];

__device__ __forceinline__ float siluf(float x) { return x / (1.f + expf(-x)); }
__device__ __forceinline__ float geluf(float x) { return 0.5f * x * (1.f + erff(x * 0.7071067811865476f)); }

template<int N> __device__ __forceinline__ void cp_wait() {
    asm volatile("cp.async.wait_group %0;\n" :: "n"(N));
}
__device__ __forceinline__ void cp_commit() {
    asm volatile("cp.async.commit_group;\n");
}

// ---------------- layer-0 in_proj LUT ----------------
__global__ void k_lut(const float* __restrict__ emb, const float* __restrict__ W) {
    __shared__ float se[8*DM];
    for (int i = threadIdx.x; i < 8*DM; i += blockDim.x) se[i] = emb[i];
    __syncthreads();
    int e = blockIdx.x*blockDim.x + threadIdx.x;
    if (e >= DIP) return;
    float acc[8] = {0.f,0.f,0.f,0.f,0.f,0.f,0.f,0.f};
    const float* wr = W + (size_t)e*DM;
    for (int d = 0; d < DM; d++) {
        float wv = wr[d];
        #pragma unroll
        for (int v = 0; v < 8; v++) acc[v] += wv * se[v*DM + d];
    }
    #pragma unroll
    for (int v = 0; v < 8; v++) g_lut[(size_t)v*DIP + e] = acc[v];
}

// ---------------- conv4 + silu + softplus(dt) + dA ----------------
template<bool LUT0>
__global__ void k_conv(const float* __restrict__ cw, const float* __restrict__ cb,
                       const float* __restrict__ dtb, const float* __restrict__ Alog,
                       const int* __restrict__ ids) {
    int bt = blockIdx.x;
    int t  = bt & (SEQ-1);
    const float* rows[4];
    #pragma unroll
    for (int k = 0; k < 4; k++) {
        int tt = t - 3 + k;
        if (tt >= 0) {
            int src = bt - 3 + k;
            rows[k] = LUT0 ? (g_lut + (size_t)ids[src]*DIP) : (g_zx + (size_t)src*DIP);
        } else rows[k] = nullptr;
    }
    for (int c = threadIdx.x; c < CDIM; c += blockDim.x) {
        float acc = cb[c];
        #pragma unroll
        for (int k = 0; k < 4; k++)
            if (rows[k]) acc += rows[k][DI + c] * cw[c*4 + k];
        g_xbc[(size_t)bt*CDIM + c] = siluf(acc);
    }
    if (threadIdx.x < NH) {
        int h = threadIdx.x;
        float xr = (LUT0 ? g_lut[(size_t)ids[bt]*DIP + DI + CDIM + h]
                         : g_zx[(size_t)bt*DIP + DI + CDIM + h]) + dtb[h];
        float dtv = (xr > 20.f) ? xr : log1pf(expf(xr));
        g_dt[bt*NH + h] = dtv;
        g_dA[bt*NH + h] = expf(dtv * (-expf(Alog[h])));
    }
}

// ---------------- phase 1: local chunk scan ----------------
__global__ void __launch_bounds__(256) k_scan1(const float* __restrict__ Dp) {
    int h = blockIdx.x, b = blockIdx.y, c = blockIdx.z;
    int tid = threadIdx.x;
    int p = tid >> 2, q = tid & 3;
    float Dh = Dp[h];
    float hreg[16];
    #pragma unroll
    for (int i = 0; i < 16; i++) hreg[i] = 0.f;
    float pi = 1.f;

    __shared__ float sx[16][64], sB[16][64], sC[16][64];
    __shared__ float sdt[16], sdA[16];

    int tbase = c*CHUNK;
    for (int tile = 0; tile < CHUNK/16; tile++) {
        int t0 = tbase + tile*16;
        for (int i = tid; i < 16*64; i += 256) {
            int s = i >> 6, j = i & 63;
            const float* row = g_xbc + (size_t)(b*SEQ + t0 + s)*CDIM;
            sx[s][j] = row[h*HD + j];
            sB[s][j] = row[DI + j];
            sC[s][j] = row[DI + NS + j];
        }
        if (tid < 16) {
            sdt[tid] = g_dt[(b*SEQ + t0 + tid)*NH + h];
            sdA[tid] = g_dA[(b*SEQ + t0 + tid)*NH + h];
        }
        __syncthreads();
        #pragma unroll 4
        for (int s = 0; s < 16; s++) {
            float da  = sdA[s];
            pi *= da;
            float xv  = sx[s][p];
            float dtx = sdt[s] * xv;
            float y = 0.f;
            #pragma unroll
            for (int i = 0; i < 16; i++) {
                int n = q + 4*i;
                hreg[i] = hreg[i]*da + dtx*sB[s][n];
                y += hreg[i]*sC[s][n];
            }
            y += __shfl_xor_sync(0xffffffffu, y, 1);
            y += __shfl_xor_sync(0xffffffffu, y, 2);
            if (q == 0)
                g_ys[(size_t)(b*SEQ + t0 + s)*DI + h*HD + p] = y + xv*Dh;
            if (tid == 0)
                g_pi[(b*SEQ + t0 + s)*NH + h] = pi;
        }
        __syncthreads();
    }
    size_t sb = ((size_t)(b*NH + h)*NCH + c)*(HD*NS);
    #pragma unroll
    for (int i = 0; i < 16; i++)
        g_S[sb + p*NS + q + 4*i] = hreg[i];
}

// ---------------- phase 2: chunk-state prefix (software-pipelined loads) ----------------
__global__ void __launch_bounds__(256) k_scan2() {
    int h = blockIdx.x, b = blockIdx.y;
    int tid = threadIdx.x;
    size_t base = (size_t)(b*NH + h)*NCH*(HD*NS);

    float Ac[NCH];
    #pragma unroll
    for (int c = 0; c < NCH; c++)
        Ac[c] = g_pi[(b*SEQ + c*CHUNK + CHUNK-1)*NH + h];

    float H[16], Sc[16];
    #pragma unroll
    for (int j = 0; j < 16; j++) H[j] = 0.f;
    #pragma unroll
    for (int j = 0; j < 16; j++) Sc[j] = g_S[base + tid*16 + j];

    #pragma unroll
    for (int c = 0; c < NCH; c++) {
        float Sn[16];
        if (c + 1 < NCH) {
            size_t noff = base + (size_t)(c+1)*(HD*NS) + tid*16;
            #pragma unroll
            for (int j = 0; j < 16; j++) Sn[j] = g_S[noff + j];
        }
        size_t off = base + (size_t)c*(HD*NS) + tid*16;
        #pragma unroll
        for (int j = 0; j < 16; j++) {
            float hp = H[j];
            g_S[off + j] = hp;
            H[j] = Ac[c]*hp + Sc[j];
        }
        #pragma unroll
        for (int j = 0; j < 16; j++) Sc[j] = Sn[j];
    }
}

// ---------------- phase 3: cross-chunk correction ----------------
__global__ void __launch_bounds__(256) k_scan3() {
    int h = blockIdx.x, b = blockIdx.y, c = blockIdx.z + 1;
    int tid = threadIdx.x;
    int pp = tid & 63, g = tid >> 6;

    __shared__ float sH[64][65];
    __shared__ float sC[16][64];
    __shared__ float spi[16];

    size_t hb = ((size_t)(b*NH + h)*NCH + c)*(HD*NS);
    for (int e = tid; e < HD*NS; e += 256)
        sH[e >> 6][e & 63] = g_S[hb + e];

    for (int tile = 0; tile < CHUNK/16; tile++) {
        int t0 = c*CHUNK + tile*16;
        __syncthreads();
        for (int i = tid; i < 16*64; i += 256) {
            int s = i >> 6, n = i & 63;
            sC[s][n] = g_xbc[(size_t)(b*SEQ + t0 + s)*CDIM + DI + NS + n];
        }
        if (tid < 16)
            spi[tid] = g_pi[(b*SEQ + t0 + tid)*NH + h];
        __syncthreads();
        #pragma unroll
        for (int u = 0; u < 4; u++) {
            int s = g*4 + u;
            float y = 0.f;
            #pragma unroll 16
            for (int n = 0; n < 64; n++)
                y += sC[s][n]*sH[pp][n];
            g_ys[(size_t)(b*SEQ + t0 + s)*DI + h*HD + pp] += spi[s]*y;
        }
    }
}

// ---------------- gate + RMSNorm -> fp16 pair g_a2 = [Ah | Al] ----------------
template<bool LUT0>
__global__ void k_gate(const float* __restrict__ nw, const int* __restrict__ ids) {
    int bt = blockIdx.x, tid = threadIdx.x;
    const float* ysr = g_ys + (size_t)bt*DI;
    const float* zr  = LUT0 ? (g_lut + (size_t)ids[bt]*DIP) : (g_zx + (size_t)bt*DIP);
    float v0 = ysr[tid]       * siluf(zr[tid]);
    float v1 = ysr[tid + 256] * siluf(zr[tid + 256]);
    __shared__ float red[256];
    red[tid] = v0*v0 + v1*v1;
    __syncthreads();
    for (int s = 128; s > 0; s >>= 1) {
        if (tid < s) red[tid] += red[tid + s];
        __syncthreads();
    }
    float scale = rsqrtf(red[0] * (1.f/DI) + 1e-5f);
    __half* a2 = g_a2 + (size_t)bt*(2*DI);
    float y0 = v0*scale*nw[tid];
    float y1 = v1*scale*nw[tid + 256];
    __half h0 = __float2half_rn(y0);
    __half l0 = __float2half_rn(y0 - __half2float(h0));
    __half h1 = __float2half_rn(y1);
    __half l1 = __float2half_rn(y1 - __half2float(h1));
    a2[tid] = h0;       a2[DI + tid] = l0;
    a2[tid + 256] = h1; a2[DI + tid + 256] = l1;
}

// ---------------- weight pair conversion: W2 = [Wf | Wf] ----------------
__global__ void k_cvtW(const float* __restrict__ W, __half* __restrict__ W2,
                       int N, int Npad, int K) {
    int idx = blockIdx.x*blockDim.x + threadIdx.x;
    if (idx >= Npad*K) return;
    int n = idx / K, k = idx % K;
    float w = (n < N) ? W[(size_t)n*K + k] : 0.f;
    __half hf = __float2half_rn(w);
    __half* row = W2 + (size_t)n*(2*K);
    row[k] = hf; row[K + k] = hf;
}

// ---------------- 3-stage pipelined tensor-core GEMM (mma.sync fp16, fp32 acc) ----------------
// RESID_MODE: 0 none, 1 add R[m][n], 2 add emb[ids[m]][n]
#define GBM 128
#define GBN 128
#define GBK 32
#define STG 3
#define LDA (GBK+8)
#define SMEM_MMA (STG*2*GBM*LDA*2)

template<int RESID_MODE, bool X2OUT>
__global__ void __launch_bounds__(256) k_mma(
        const __half* __restrict__ A,
        const __half* __restrict__ W,
        const float* __restrict__ R,
        const int* __restrict__ ids,
        const float* __restrict__ emb,
        float* __restrict__ C,
        __half* __restrict__ X2,
        int N, int Kp, int ldc)
{
    extern __shared__ __half smp[];
    __half* Asm = smp;                       // [STG][GBM][LDA]
    __half* Wsm = smp + STG*GBM*LDA;

    int tid = threadIdx.x;
    int warp = tid >> 5, lane = tid & 31;
    int wm = warp >> 2, wn = warp & 3;
    int m0 = blockIdx.y * GBM;
    int n0 = blockIdx.x * GBN;

    float acc[4][4][4];
    #pragma unroll
    for (int i = 0; i < 4; i++)
        #pragma unroll
        for (int j = 0; j < 4; j++)
            #pragma unroll
            for (int e = 0; e < 4; e++) acc[i][j][e] = 0.f;

    int nk = Kp / GBK;

    auto load_stage = [&](int st, int k0) {
        __half* as = Asm + st*GBM*LDA;
        __half* ws = Wsm + st*GBM*LDA;
        #pragma unroll
        for (int u = 0; u < 2; u++) {
            int idx = tid + u*256;
            int r = idx >> 2, kc = (idx & 3)*8;
            unsigned da = (unsigned)__cvta_generic_to_shared(as + r*LDA + kc);
            asm volatile("cp.async.cg.shared.global [%0], [%1], 16;\n"
                :: "r"(da), "l"(A + (size_t)(m0 + r)*Kp + k0 + kc));
            unsigned dw = (unsigned)__cvta_generic_to_shared(ws + r*LDA + kc);
            asm volatile("cp.async.cg.shared.global [%0], [%1], 16;\n"
                :: "r"(dw), "l"(W + (size_t)(n0 + r)*Kp + k0 + kc));
        }
    };

    load_stage(0, 0);
    cp_commit();
    load_stage(1, GBK);
    cp_commit();

    for (int it = 0; it < nk; it++) {
        cp_wait<1>();
        __syncthreads();
        if (it + 2 < nk) {
            load_stage((it + 2) % STG, (it + 2)*GBK);
            cp_commit();
        } else {
            cp_commit();
        }
        int st = it % STG;
        __half* as = Asm + st*GBM*LDA;
        __half* ws = Wsm + st*GBM*LDA;

        #pragma unroll
        for (int kk = 0; kk < GBK; kk += 16) {
            unsigned af[4][4];
            #pragma unroll
            for (int i = 0; i < 4; i++) {
                int row = wm*64 + i*16 + (lane & 15);
                int col = kk + ((lane >> 4) << 3);
                unsigned addr = (unsigned)__cvta_generic_to_shared(as + row*LDA + col);
                asm volatile("ldmatrix.sync.aligned.m8n8.x4.shared.b16 {%0,%1,%2,%3}, [%4];\n"
                    : "=r"(af[i][0]), "=r"(af[i][1]), "=r"(af[i][2]), "=r"(af[i][3]) : "r"(addr));
            }
            unsigned bfm[2][4];
            #pragma unroll
            for (int g = 0; g < 2; g++) {
                int row = wn*32 + g*16 + (lane & 15);
                int col = kk + ((lane >> 4) << 3);
                unsigned addr = (unsigned)__cvta_generic_to_shared(ws + row*LDA + col);
                asm volatile("ldmatrix.sync.aligned.m8n8.x4.shared.b16 {%0,%1,%2,%3}, [%4];\n"
                    : "=r"(bfm[g][0]), "=r"(bfm[g][1]), "=r"(bfm[g][2]), "=r"(bfm[g][3]) : "r"(addr));
            }
            #pragma unroll
            for (int i = 0; i < 4; i++) {
                #pragma unroll
                for (int g = 0; g < 2; g++) {
                    #pragma unroll
                    for (int s = 0; s < 2; s++) {
                        int j = g*2 + s;
                        asm volatile(
                            "mma.sync.aligned.m16n8k16.row.col.f32.f16.f16.f32 "
                            "{%0,%1,%2,%3}, {%4,%5,%6,%7}, {%8,%9}, {%0,%1,%2,%3};\n"
                            : "+f"(acc[i][j][0]), "+f"(acc[i][j][1]),
                              "+f"(acc[i][j][2]), "+f"(acc[i][j][3])
                            : "r"(af[i][0]), "r"(af[i][1]), "r"(af[i][2]), "r"(af[i][3]),
                              "r"(bfm[g][s]), "r"(bfm[g][s+2]));
                    }
                }
            }
        }
    }

    // epilogue
    #pragma unroll
    for (int i = 0; i < 4; i++) {
        #pragma unroll
        for (int half_ = 0; half_ < 2; half_++) {
            int m = m0 + wm*64 + i*16 + (lane >> 2) + half_*8;
            const float* rrow = nullptr;
            if (RESID_MODE == 1) rrow = R + (size_t)m*ldc;
            if (RESID_MODE == 2) rrow = emb + (size_t)ids[m]*DM;
            #pragma unroll
            for (int j = 0; j < 4; j++) {
                int ncol = n0 + wn*32 + j*8 + (lane & 3)*2;
                #pragma unroll
                for (int e = 0; e < 2; e++) {
                    int n = ncol + e;
                    if (n < N) {
                        float v = acc[i][j][half_*2 + e];
                        if (RESID_MODE) v += rrow[n];
                        C[(size_t)m*ldc + n] = v;
                        if (X2OUT) {
                            __half hh = __float2half_rn(v);
                            __half ll = __float2half_rn(v - __half2float(hh));
                            __half* row = X2 + (size_t)m*(2*N);
                            row[n] = hh; row[N + n] = ll;
                        }
                    }
                }
            }
        }
    }
}

// ---------------- pooling ----------------
__global__ void k_pool1() {
    int seg = blockIdx.x, b = blockIdx.y, d = threadIdx.x;
    float sum = 0.f, mx = -INFINITY;
    for (int i = 0; i < 64; i++) {
        float v = g_x[(size_t)(b*SEQ + seg*64 + i)*DM + d];
        sum += v; mx = fmaxf(mx, v);
    }
    g_psum[(b*16 + seg)*DM + d] = sum;
    g_pmax[(b*16 + seg)*DM + d] = mx;
}
__global__ void k_pool2() {
    int b = blockIdx.x, d = threadIdx.x;
    float sum = 0.f, mx = -INFINITY;
    for (int s = 0; s < 16; s++) {
        sum += g_psum[(b*16 + s)*DM + d];
        mx = fmaxf(mx, g_pmax[(b*16 + s)*DM + d]);
    }
    g_pooled[b*DM + d] = (sum*(1.f/SEQ) + mx)*0.5f;
}

// ---------------- classification head ----------------
__global__ void k_head(const float* __restrict__ pw, const float* __restrict__ pb,
                       const float* __restrict__ c1w, const float* __restrict__ c1b,
                       const float* __restrict__ c2w, const float* __restrict__ c2b,
                       float* __restrict__ out) {
    int b = blockIdx.x, tid = threadIdx.x;
    __shared__ float sp[DM], s1[DM], s2[128];
    sp[tid] = g_pooled[b*DM + tid];
    __syncthreads();
    {
        float acc = pb[tid];
        const float* wr = pw + (size_t)tid*DM;
        for (int d = 0; d < DM; d++) acc += sp[d]*wr[d];
        s1[tid] = geluf(acc);
    }
    __syncthreads();
    if (tid < 128) {
        float acc = c1b[tid];
        const float* wr = c1w + (size_t)tid*DM;
        for (int d = 0; d < DM; d++) acc += s1[d]*wr[d];
        s2[tid] = geluf(acc);
    }
    __syncthreads();
    if (tid < 2) {
        float acc = c2b[tid];
        const float* wr = c2w + tid*128;
        for (int d = 0; d < 128; d++) acc += s2[d]*wr[d];
        out[b*2 + tid] = acc;
    }
}

// ---------------- launch ----------------
extern "C" void kernel_launch(void* const* d_in, const int* in_sizes, int n_in,
                              void* d_out, int out_size) {
    const int*   ids  = (const int*)  d_in[0];
    const float* emb  = (const float*)d_in[1];
    const float* inw  = (const float*)d_in[2];
    const float* cw   = (const float*)d_in[3];
    const float* cb   = (const float*)d_in[4];
    const float* dtb  = (const float*)d_in[5];
    const float* alog = (const float*)d_in[6];
    const float* Dv   = (const float*)d_in[7];
    const float* nw   = (const float*)d_in[8];
    const float* ow   = (const float*)d_in[9];
    const float* pw   = (const float*)d_in[10];
    const float* pb   = (const float*)d_in[11];
    const float* c1w  = (const float*)d_in[12];
    const float* c1b  = (const float*)d_in[13];
    const float* c2w  = (const float*)d_in[14];
    const float* c2b  = (const float*)d_in[15];
    float* out = (float*)d_out;

    float *px, *pzx;
    __half *pa2, *px2, *pw2a, *pw2b;
    cudaGetSymbolAddress((void**)&px,   g_x);
    cudaGetSymbolAddress((void**)&pzx,  g_zx);
    cudaGetSymbolAddress((void**)&pa2,  g_a2);
    cudaGetSymbolAddress((void**)&px2,  g_x2);
    cudaGetSymbolAddress((void**)&pw2a, g_w2a);
    cudaGetSymbolAddress((void**)&pw2b, g_w2b);

    cudaFuncSetAttribute(k_mma<2, true>,
        cudaFuncAttributeMaxDynamicSharedMemorySize, SMEM_MMA);
    cudaFuncSetAttribute(k_mma<0, false>,
        cudaFuncAttributeMaxDynamicSharedMemorySize, SMEM_MMA);
    cudaFuncSetAttribute(k_mma<1, false>,
        cudaFuncAttributeMaxDynamicSharedMemorySize, SMEM_MMA);

    // ---- layer 0 (w2a convert moved first so launch #4 = k_scan1 for profiling) ----
    k_cvtW<<<(NPAD_IN*DM + 255)/256, 256>>>(inw + (size_t)DIP*DM, pw2a, DIP, NPAD_IN, DM);
    k_lut<<<(DIP + 255)/256, 256>>>(emb, inw);
    k_conv<true><<<NTOK, 256>>>(cw, cb, dtb, alog, ids);
    k_scan1<<<dim3(NH, BATCH, NCH), 256>>>(Dv);
    k_scan2<<<dim3(NH, BATCH), 256>>>();
    k_scan3<<<dim3(NH, BATCH, NCH-1), 256>>>();
    k_gate<true><<<NTOK, 256>>>(nw, ids);
    k_cvtW<<<(DM*DI + 255)/256, 256>>>(ow, pw2b, DM, DM, DI);
    // out_proj l0: M=8192, N=256, Kp=1024; residual = emb[ids]; emit x2 pair
    k_mma<2, true><<<dim3(DM/GBN, NTOK/GBM), 256, SMEM_MMA>>>(
        pa2, pw2b, nullptr, ids, emb, px, px2, DM, 2*DI, DM);

    // ---- layer 1 ----
    // in_proj: M=8192, N=1160 (pad 1280), Kp=512
    k_mma<0, false><<<dim3(NPAD_IN/GBN, NTOK/GBM), 256, SMEM_MMA>>>(
        px2, pw2a, nullptr, nullptr, nullptr, pzx, nullptr, DIP, 2*DM, DIP);
    k_conv<false><<<NTOK, 256>>>(cw + (size_t)CDIM*4, cb + CDIM, dtb + NH, alog + NH, ids);
    k_scan1<<<dim3(NH, BATCH, NCH), 256>>>(Dv + NH);
    k_scan2<<<dim3(NH, BATCH), 256>>>();
    k_scan3<<<dim3(NH, BATCH, NCH-1), 256>>>();
    k_gate<false><<<NTOK, 256>>>(nw + DI, ids);
    k_cvtW<<<(DM*DI + 255)/256, 256>>>(ow + (size_t)DM*DI, pw2b, DM, DM, DI);
    k_mma<1, false><<<dim3(DM/GBN, NTOK/GBM), 256, SMEM_MMA>>>(
        pa2, pw2b, px, nullptr, nullptr, px, nullptr, DM, 2*DI, DM);

    k_pool1<<<dim3(16, BATCH), DM>>>();
    k_pool2<<<BATCH, DM>>>();
    k_head<<<BATCH, DM>>>(pw, pb, c1w, c1b, c2w, c2b, out);
}